// round 1
// baseline (speedup 1.0000x reference)
#include <cuda_runtime.h>
#include <math.h>

#define B_  2
#define S_  2048
#define H_  16
#define DH_ 64
#define D_  1024
#define M_  (B_*S_)   // 4096 rows

// Scratch (allocation-free rule: __device__ globals)
__device__ float g_Q[M_*D_];
__device__ float g_K[M_*D_];
__device__ float g_V[M_*D_];
__device__ float g_A[M_*D_];

// ---------------------------------------------------------------------------
// C[M][N] = A[M][K] @ W[N][K]^T + bias[N]      (torch Linear)
// 64x64 tile, BK=16, 256 threads, 4x4 per thread
// ---------------------------------------------------------------------------
__global__ __launch_bounds__(256) void gemm_xwt(
    const float* __restrict__ A, const float* __restrict__ W,
    const float* __restrict__ bias, float* __restrict__ C,
    int M, int N, int K)
{
    __shared__ float As[64][17];
    __shared__ float Bs[64][17];

    const int tid = threadIdx.x;
    const int tx  = tid & 15;        // 0..15 -> output cols
    const int ty  = tid >> 4;        // 0..15 -> output rows
    const int m0  = blockIdx.y * 64;
    const int n0  = blockIdx.x * 64;

    const int lrow = tid >> 2;       // 0..63
    const int lcol = (tid & 3) * 4;  // 0,4,8,12

    float acc[4][4];
#pragma unroll
    for (int i = 0; i < 4; i++)
#pragma unroll
        for (int j = 0; j < 4; j++) acc[i][j] = 0.f;

    for (int k0 = 0; k0 < K; k0 += 16) {
        float4 av = *(const float4*)(A + (size_t)(m0 + lrow) * K + k0 + lcol);
        float4 wv = *(const float4*)(W + (size_t)(n0 + lrow) * K + k0 + lcol);
        As[lrow][lcol+0] = av.x; As[lrow][lcol+1] = av.y;
        As[lrow][lcol+2] = av.z; As[lrow][lcol+3] = av.w;
        Bs[lrow][lcol+0] = wv.x; Bs[lrow][lcol+1] = wv.y;
        Bs[lrow][lcol+2] = wv.z; Bs[lrow][lcol+3] = wv.w;
        __syncthreads();

#pragma unroll
        for (int kk = 0; kk < 16; kk++) {
            float a[4], b[4];
#pragma unroll
            for (int i = 0; i < 4; i++) a[i] = As[ty*4+i][kk];
#pragma unroll
            for (int j = 0; j < 4; j++) b[j] = Bs[tx*4+j][kk];
#pragma unroll
            for (int i = 0; i < 4; i++)
#pragma unroll
                for (int j = 0; j < 4; j++) acc[i][j] += a[i] * b[j];
        }
        __syncthreads();
    }

#pragma unroll
    for (int i = 0; i < 4; i++) {
        float* crow = C + (size_t)(m0 + ty*4 + i) * N + n0;
#pragma unroll
        for (int j = 0; j < 4; j++)
            crow[tx*4+j] = acc[i][j] + bias[n0 + tx*4 + j];
    }
}

// ---------------------------------------------------------------------------
// Flash-style attention. Grid: (S/64 query tiles, B*H). 256 threads.
// Each quad of 4 threads owns one query row; 32-key tiles; online softmax.
// Masked keys get score -1e30 (sentinel avoids -inf NaN paths; an all-masked
// running max yields garbage that is exactly zeroed by alpha once a real key
// appears, and p underflows to 0 for masked cols otherwise).
// ---------------------------------------------------------------------------
__global__ __launch_bounds__(256) void attn_kernel(
    const float* __restrict__ Q, const float* __restrict__ K,
    const float* __restrict__ V, const int* __restrict__ mask,
    float* __restrict__ Aout)
{
    const int bh = blockIdx.y;
    const int b  = bh / H_;
    const int h  = bh % H_;
    const int q0 = blockIdx.x * 64;

    const int tid = threadIdx.x;
    const int r   = tid >> 2;    // query row in tile, 0..63
    const int q   = tid & 3;     // quad lane

    __shared__ float Qs[64][65];
    __shared__ float Ks[32][65];
    __shared__ float Vs[32][65];
    __shared__ float Ps[64][33];
    __shared__ float Ms[32];

    // Load Q tile (64 x 64)
    {
        const float* Qb = Q + ((size_t)(b*S_ + q0)) * D_ + h*DH_;
#pragma unroll
        for (int it = 0; it < 4; it++) {
            int idx = tid + it*256;        // float4 index, 0..1023
            int fr = idx >> 4, fc = (idx & 15) * 4;
            float4 v4 = *(const float4*)(Qb + (size_t)fr * D_ + fc);
            Qs[fr][fc+0] = v4.x; Qs[fr][fc+1] = v4.y;
            Qs[fr][fc+2] = v4.z; Qs[fr][fc+3] = v4.w;
        }
    }

    const float scale = 0.125f;  // 1/sqrt(64)
    float m_run = -1e30f, l_run = 0.f;
    float o[16];
#pragma unroll
    for (int jj = 0; jj < 16; jj++) o[jj] = 0.f;

    const float* Kb0 = K + ((size_t)b*S_) * D_ + h*DH_;
    const float* Vb0 = V + ((size_t)b*S_) * D_ + h*DH_;

    for (int kt = 0; kt < S_; kt += 32) {
        __syncthreads();   // protect Ks/Vs/Ms from previous iteration readers
        // Load K,V tiles (32 x 64 each) + mask
        {
            const float* Kb = Kb0 + (size_t)kt * D_;
            const float* Vb = Vb0 + (size_t)kt * D_;
#pragma unroll
            for (int it = 0; it < 2; it++) {
                int idx = tid + it*256;    // 0..511 float4s
                int fr = idx >> 4, fc = (idx & 15) * 4;
                float4 kv = *(const float4*)(Kb + (size_t)fr * D_ + fc);
                float4 vv = *(const float4*)(Vb + (size_t)fr * D_ + fc);
                Ks[fr][fc+0] = kv.x; Ks[fr][fc+1] = kv.y;
                Ks[fr][fc+2] = kv.z; Ks[fr][fc+3] = kv.w;
                Vs[fr][fc+0] = vv.x; Vs[fr][fc+1] = vv.y;
                Vs[fr][fc+2] = vv.z; Vs[fr][fc+3] = vv.w;
            }
            if (tid < 32) Ms[tid] = (float)mask[(size_t)b*S_ + kt + tid];
        }
        __syncthreads();

        // Scores: this thread owns key cols c = q + 4*j, j=0..7
        float s[8];
#pragma unroll
        for (int j = 0; j < 8; j++) s[j] = 0.f;
#pragma unroll 8
        for (int d = 0; d < 64; d++) {
            float qv = Qs[r][d];
#pragma unroll
            for (int j = 0; j < 8; j++) s[j] += qv * Ks[q + 4*j][d];
        }

        float mtile = -1e30f;
#pragma unroll
        for (int j = 0; j < 8; j++) {
            float sc = s[j] * scale;
            sc = (Ms[q + 4*j] != 0.f) ? sc : -1e30f;
            s[j] = sc;
            mtile = fmaxf(mtile, sc);
        }
        mtile = fmaxf(mtile, __shfl_xor_sync(0xffffffffu, mtile, 1));
        mtile = fmaxf(mtile, __shfl_xor_sync(0xffffffffu, mtile, 2));

        float mnew  = fmaxf(m_run, mtile);
        float alpha = __expf(m_run - mnew);

        float psum = 0.f;
#pragma unroll
        for (int j = 0; j < 8; j++) {
            float p = __expf(s[j] - mnew);
            s[j] = p;
            psum += p;
        }
        psum += __shfl_xor_sync(0xffffffffu, psum, 1);
        psum += __shfl_xor_sync(0xffffffffu, psum, 2);

        l_run = l_run * alpha + psum;
        m_run = mnew;

#pragma unroll
        for (int j = 0; j < 8; j++) Ps[r][q + 4*j] = s[j];
#pragma unroll
        for (int jj = 0; jj < 16; jj++) o[jj] *= alpha;
        __syncwarp();

        // O accumulation: this thread owns dims d = q + 4*jj
#pragma unroll 4
        for (int c = 0; c < 32; c++) {
            float pv = Ps[r][c];
#pragma unroll
            for (int jj = 0; jj < 16; jj++) o[jj] += pv * Vs[c][q + 4*jj];
        }
        __syncwarp();
    }

    // Epilogue
    float inv_l = 1.f / l_run;
    float* Ab = Aout + ((size_t)(b*S_ + q0 + r)) * D_ + h*DH_;
#pragma unroll
    for (int jj = 0; jj < 16; jj++) Ab[q + 4*jj] = o[jj] * inv_l;
}

// ---------------------------------------------------------------------------
extern "C" void kernel_launch(void* const* d_in, const int* in_sizes, int n_in,
                              void* d_out, int out_size)
{
    const float* x    = (const float*)d_in[0];
    const int*   mask = (const int*)  d_in[1];
    const float* Wq   = (const float*)d_in[2];
    const float* bq   = (const float*)d_in[3];
    const float* Wk   = (const float*)d_in[4];
    const float* bk   = (const float*)d_in[5];
    const float* Wv   = (const float*)d_in[6];
    const float* bv   = (const float*)d_in[7];
    const float* Wo   = (const float*)d_in[8];
    const float* bo   = (const float*)d_in[9];
    float* out = (float*)d_out;

    float *qb, *kb, *vb, *ab;
    cudaGetSymbolAddress((void**)&qb, g_Q);
    cudaGetSymbolAddress((void**)&kb, g_K);
    cudaGetSymbolAddress((void**)&vb, g_V);
    cudaGetSymbolAddress((void**)&ab, g_A);

    dim3 gg(D_/64, M_/64);   // (16, 64)
    gemm_xwt<<<gg, 256>>>(x, Wq, bq, qb, M_, D_, D_);
    gemm_xwt<<<gg, 256>>>(x, Wk, bk, kb, M_, D_, D_);
    gemm_xwt<<<gg, 256>>>(x, Wv, bv, vb, M_, D_, D_);

    dim3 ga(S_/64, B_*H_);   // (32, 32)
    attn_kernel<<<ga, 256>>>(qb, kb, vb, mask, ab);

    gemm_xwt<<<gg, 256>>>(ab, Wo, bo, out, M_, D_, D_);
}

// round 2
// speedup vs baseline: 1.7454x; 1.7454x over previous
#include <cuda_runtime.h>
#include <math.h>

#define B_  2
#define S_  2048
#define H_  16
#define DH_ 64
#define D_  1024
#define M_  (B_*S_)   // 4096 rows

// Scratch (allocation-free rule: __device__ globals)
__device__ float g_Q[M_*D_];
__device__ float g_K[M_*D_];
__device__ float g_V[M_*D_];
__device__ float g_A[M_*D_];

// ---------------------------------------------------------------------------
// C[M][N] = A[M][K] @ W[N][K]^T + bias[N]   (torch Linear)
// 128x128 block tile, BK=16, 256 threads, 8x8 per-thread micro-tile,
// double-buffered smem with register prefetch. M=4096, N=K=1024 fixed.
// ---------------------------------------------------------------------------
__global__ __launch_bounds__(256, 2) void gemm_xwt(
    const float* __restrict__ A, const float* __restrict__ W,
    const float* __restrict__ bias, float* __restrict__ C)
{
    const int K = D_, N = D_;
    __shared__ float As[2][16][132];
    __shared__ float Bs[2][16][132];

    const int tid = threadIdx.x;
    const int tx  = tid & 15;
    const int ty  = tid >> 4;
    const int m0  = blockIdx.y * 128;
    const int n0  = blockIdx.x * 128;

    const int r0 = tid >> 2;          // 0..63
    const int r1 = 64 + r0;           // 64..127
    const int kq = (tid & 3) * 4;     // 0,4,8,12

    const float* pA0 = A + (size_t)(m0 + r0) * K + kq;
    const float* pA1 = A + (size_t)(m0 + r1) * K + kq;
    const float* pW0 = W + (size_t)(n0 + r0) * K + kq;
    const float* pW1 = W + (size_t)(n0 + r1) * K + kq;

    float acc[8][8];
#pragma unroll
    for (int i = 0; i < 8; i++)
#pragma unroll
        for (int j = 0; j < 8; j++) acc[i][j] = 0.f;

    // preload k-tile 0 into buffer 0
    {
        float4 a0 = *(const float4*)pA0;
        float4 a1 = *(const float4*)pA1;
        float4 b0 = *(const float4*)pW0;
        float4 b1 = *(const float4*)pW1;
        As[0][kq+0][r0] = a0.x; As[0][kq+1][r0] = a0.y; As[0][kq+2][r0] = a0.z; As[0][kq+3][r0] = a0.w;
        As[0][kq+0][r1] = a1.x; As[0][kq+1][r1] = a1.y; As[0][kq+2][r1] = a1.z; As[0][kq+3][r1] = a1.w;
        Bs[0][kq+0][r0] = b0.x; Bs[0][kq+1][r0] = b0.y; Bs[0][kq+2][r0] = b0.z; Bs[0][kq+3][r0] = b0.w;
        Bs[0][kq+0][r1] = b1.x; Bs[0][kq+1][r1] = b1.y; Bs[0][kq+2][r1] = b1.z; Bs[0][kq+3][r1] = b1.w;
    }
    __syncthreads();

    const int KT = K / 16;   // 64
    for (int kt = 0; kt < KT; kt++) {
        const int cur = kt & 1;
        float4 a0, a1, b0, b1;
        if (kt + 1 < KT) {
            const int off = (kt + 1) * 16;
            a0 = *(const float4*)(pA0 + off);
            a1 = *(const float4*)(pA1 + off);
            b0 = *(const float4*)(pW0 + off);
            b1 = *(const float4*)(pW1 + off);
        }

#pragma unroll
        for (int kk = 0; kk < 16; kk++) {
            float a[8], b[8];
            *(float4*)(a)     = *(const float4*)&As[cur][kk][ty*8];
            *(float4*)(a + 4) = *(const float4*)&As[cur][kk][ty*8 + 4];
            *(float4*)(b)     = *(const float4*)&Bs[cur][kk][tx*8];
            *(float4*)(b + 4) = *(const float4*)&Bs[cur][kk][tx*8 + 4];
#pragma unroll
            for (int i = 0; i < 8; i++)
#pragma unroll
                for (int j = 0; j < 8; j++) acc[i][j] += a[i] * b[j];
        }

        if (kt + 1 < KT) {
            const int nxt = cur ^ 1;
            As[nxt][kq+0][r0] = a0.x; As[nxt][kq+1][r0] = a0.y; As[nxt][kq+2][r0] = a0.z; As[nxt][kq+3][r0] = a0.w;
            As[nxt][kq+0][r1] = a1.x; As[nxt][kq+1][r1] = a1.y; As[nxt][kq+2][r1] = a1.z; As[nxt][kq+3][r1] = a1.w;
            Bs[nxt][kq+0][r0] = b0.x; Bs[nxt][kq+1][r0] = b0.y; Bs[nxt][kq+2][r0] = b0.z; Bs[nxt][kq+3][r0] = b0.w;
            Bs[nxt][kq+0][r1] = b1.x; Bs[nxt][kq+1][r1] = b1.y; Bs[nxt][kq+2][r1] = b1.z; Bs[nxt][kq+3][r1] = b1.w;
            __syncthreads();
        }
    }

    // epilogue: add bias, store
    float bv[8];
#pragma unroll
    for (int j = 0; j < 8; j++) bv[j] = bias[n0 + tx*8 + j];
#pragma unroll
    for (int i = 0; i < 8; i++) {
        float* crow = C + (size_t)(m0 + ty*8 + i) * N + n0 + tx*8;
        float4 o0, o1;
        o0.x = acc[i][0] + bv[0]; o0.y = acc[i][1] + bv[1];
        o0.z = acc[i][2] + bv[2]; o0.w = acc[i][3] + bv[3];
        o1.x = acc[i][4] + bv[4]; o1.y = acc[i][5] + bv[5];
        o1.z = acc[i][6] + bv[6]; o1.w = acc[i][7] + bv[7];
        *(float4*)(crow)     = o0;
        *(float4*)(crow + 4) = o1;
    }
}

// ---------------------------------------------------------------------------
// Flash attention: 128 queries x 128-key tiles per CTA. 256 threads (16x16).
// Score stage: 8x8 micro-tile per thread (64 FMA / 4 LDS.128).
// PV stage: 8 q-rows x 4 d-cols per thread, P staged in smem.
// Online softmax, per-thread state for its 8 query rows.
// ---------------------------------------------------------------------------
#define QK_PITCH 132
#define V_PITCH  68
#define P_PITCH  132
#define SMEM_ATTN ((64*QK_PITCH*2 + 128*V_PITCH + 128*P_PITCH + 128) * 4)

__global__ __launch_bounds__(256, 1) void attn_kernel(
    const float* __restrict__ Q, const float* __restrict__ K,
    const float* __restrict__ V, const int* __restrict__ mask,
    float* __restrict__ Aout)
{
    extern __shared__ float sm[];
    float* Qst = sm;                        // [64][QK_PITCH] d-major
    float* Kst = Qst + 64 * QK_PITCH;       // [64][QK_PITCH] d-major
    float* Vs  = Kst + 64 * QK_PITCH;       // [128][V_PITCH] row-major
    float* Ps  = Vs  + 128 * V_PITCH;       // [128][P_PITCH] row-major
    float* Msk = Ps  + 128 * P_PITCH;       // [128]

    const int bh = blockIdx.y;
    const int b  = bh / H_;
    const int h  = bh % H_;
    const int q0 = blockIdx.x * 128;

    const int tid = threadIdx.x;
    const int tx  = tid & 15;
    const int ty  = tid >> 4;

    // ---- load Q tile (128 q x 64 d), transposed into Qst[d][q] ----
    {
        const float* Qb = Q + ((size_t)(b*S_ + q0)) * D_ + h*DH_;
#pragma unroll
        for (int it = 0; it < 8; it++) {
            int f  = tid + it * 256;
            int qr = f >> 4;
            int dq = (f & 15) * 4;
            float4 v = *(const float4*)(Qb + (size_t)qr * D_ + dq);
            Qst[(dq+0)*QK_PITCH + qr] = v.x;
            Qst[(dq+1)*QK_PITCH + qr] = v.y;
            Qst[(dq+2)*QK_PITCH + qr] = v.z;
            Qst[(dq+3)*QK_PITCH + qr] = v.w;
        }
    }

    const float scale = 0.125f;   // 1/sqrt(64)
    float m_run[8], l_run[8], o[8][4];
#pragma unroll
    for (int i = 0; i < 8; i++) {
        m_run[i] = -1e30f; l_run[i] = 0.f;
#pragma unroll
        for (int j = 0; j < 4; j++) o[i][j] = 0.f;
    }

    const float* Kb0 = K + ((size_t)b*S_) * D_ + h*DH_;
    const float* Vb0 = V + ((size_t)b*S_) * D_ + h*DH_;

    for (int kt = 0; kt < S_; kt += 128) {
        __syncthreads();   // previous PV done; Q store done (first iter)

        // ---- load K tile (transposed), V tile (row-major), mask ----
        {
            const float* Kb = Kb0 + (size_t)kt * D_;
            const float* Vb = Vb0 + (size_t)kt * D_;
#pragma unroll
            for (int it = 0; it < 8; it++) {
                int f  = tid + it * 256;
                int kr = f >> 4;
                int dq = (f & 15) * 4;
                float4 kv = *(const float4*)(Kb + (size_t)kr * D_ + dq);
                float4 vv = *(const float4*)(Vb + (size_t)kr * D_ + dq);
                Kst[(dq+0)*QK_PITCH + kr] = kv.x;
                Kst[(dq+1)*QK_PITCH + kr] = kv.y;
                Kst[(dq+2)*QK_PITCH + kr] = kv.z;
                Kst[(dq+3)*QK_PITCH + kr] = kv.w;
                Vs[kr*V_PITCH + dq + 0] = vv.x;
                Vs[kr*V_PITCH + dq + 1] = vv.y;
                Vs[kr*V_PITCH + dq + 2] = vv.z;
                Vs[kr*V_PITCH + dq + 3] = vv.w;
            }
            if (tid < 128) Msk[tid] = (float)mask[(size_t)b*S_ + kt + tid];
        }
        __syncthreads();

        // ---- scores: s[8][8], rows ty*8+i, cols tx*8+j ----
        float s[8][8];
#pragma unroll
        for (int i = 0; i < 8; i++)
#pragma unroll
            for (int j = 0; j < 8; j++) s[i][j] = 0.f;

#pragma unroll 4
        for (int d = 0; d < 64; d++) {
            float a[8], bb[8];
            *(float4*)(a)      = *(const float4*)&Qst[d*QK_PITCH + ty*8];
            *(float4*)(a + 4)  = *(const float4*)&Qst[d*QK_PITCH + ty*8 + 4];
            *(float4*)(bb)     = *(const float4*)&Kst[d*QK_PITCH + tx*8];
            *(float4*)(bb + 4) = *(const float4*)&Kst[d*QK_PITCH + tx*8 + 4];
#pragma unroll
            for (int i = 0; i < 8; i++)
#pragma unroll
                for (int j = 0; j < 8; j++) s[i][j] += a[i] * bb[j];
        }

        // mask + scale
        float mk[8];
#pragma unroll
        for (int j = 0; j < 8; j++) mk[j] = Msk[tx*8 + j];

        float mt[8];
#pragma unroll
        for (int i = 0; i < 8; i++) {
            float rm = -1e30f;
#pragma unroll
            for (int j = 0; j < 8; j++) {
                float sc = s[i][j] * scale;
                sc = (mk[j] != 0.f) ? sc : -1e30f;
                s[i][j] = sc;
                rm = fmaxf(rm, sc);
            }
            mt[i] = rm;
        }
        // reduce row max across the 16 tx lanes (within 16-lane half-warp)
#pragma unroll
        for (int i = 0; i < 8; i++) {
            float v = mt[i];
            v = fmaxf(v, __shfl_xor_sync(0xffffffffu, v, 1));
            v = fmaxf(v, __shfl_xor_sync(0xffffffffu, v, 2));
            v = fmaxf(v, __shfl_xor_sync(0xffffffffu, v, 4));
            v = fmaxf(v, __shfl_xor_sync(0xffffffffu, v, 8));
            mt[i] = v;
        }

        float alpha[8], rs[8];
#pragma unroll
        for (int i = 0; i < 8; i++) {
            float mnew = fmaxf(m_run[i], mt[i]);
            alpha[i]   = __expf(m_run[i] - mnew);
            m_run[i]   = mnew;
            float acc = 0.f;
#pragma unroll
            for (int j = 0; j < 8; j++) {
                float p = __expf(s[i][j] - mnew);
                s[i][j] = p;
                acc += p;
            }
            rs[i] = acc;
        }
#pragma unroll
        for (int i = 0; i < 8; i++) {
            float v = rs[i];
            v += __shfl_xor_sync(0xffffffffu, v, 1);
            v += __shfl_xor_sync(0xffffffffu, v, 2);
            v += __shfl_xor_sync(0xffffffffu, v, 4);
            v += __shfl_xor_sync(0xffffffffu, v, 8);
            l_run[i] = l_run[i] * alpha[i] + v;
        }

        // rescale O, stage P
#pragma unroll
        for (int i = 0; i < 8; i++) {
#pragma unroll
            for (int j = 0; j < 4; j++) o[i][j] *= alpha[i];
            *(float4*)&Ps[(ty*8+i)*P_PITCH + tx*8]     = *(float4*)&s[i][0];
            *(float4*)&Ps[(ty*8+i)*P_PITCH + tx*8 + 4] = *(float4*)&s[i][4];
        }
        __syncthreads();

        // ---- PV: O[q=ty*8+i][d=tx*4+j] += P[q][c] * V[c][d] ----
#pragma unroll 2
        for (int c = 0; c < 128; c++) {
            float4 vb = *(const float4*)&Vs[c*V_PITCH + tx*4];
#pragma unroll
            for (int i = 0; i < 8; i++) {
                float p = Ps[(ty*8+i)*P_PITCH + c];
                o[i][0] += p * vb.x;
                o[i][1] += p * vb.y;
                o[i][2] += p * vb.z;
                o[i][3] += p * vb.w;
            }
        }
    }

    // ---- epilogue ----
#pragma unroll
    for (int i = 0; i < 8; i++) {
        float inv = 1.f / l_run[i];
        float4 r;
        r.x = o[i][0]*inv; r.y = o[i][1]*inv; r.z = o[i][2]*inv; r.w = o[i][3]*inv;
        float* dst = Aout + ((size_t)(b*S_ + q0 + ty*8 + i)) * D_ + h*DH_ + tx*4;
        *(float4*)dst = r;
    }
}

// ---------------------------------------------------------------------------
extern "C" void kernel_launch(void* const* d_in, const int* in_sizes, int n_in,
                              void* d_out, int out_size)
{
    const float* x    = (const float*)d_in[0];
    const int*   mask = (const int*)  d_in[1];
    const float* Wq   = (const float*)d_in[2];
    const float* bq   = (const float*)d_in[3];
    const float* Wk   = (const float*)d_in[4];
    const float* bk   = (const float*)d_in[5];
    const float* Wv   = (const float*)d_in[6];
    const float* bv   = (const float*)d_in[7];
    const float* Wo   = (const float*)d_in[8];
    const float* bo   = (const float*)d_in[9];
    float* out = (float*)d_out;

    float *qb, *kb, *vb, *ab;
    cudaGetSymbolAddress((void**)&qb, g_Q);
    cudaGetSymbolAddress((void**)&kb, g_K);
    cudaGetSymbolAddress((void**)&vb, g_V);
    cudaGetSymbolAddress((void**)&ab, g_A);

    cudaFuncSetAttribute(attn_kernel,
                         cudaFuncAttributeMaxDynamicSharedMemorySize, SMEM_ATTN);

    dim3 gg(D_/128, M_/128);   // (8, 32)
    gemm_xwt<<<gg, 256>>>(x, Wq, bq, qb);
    gemm_xwt<<<gg, 256>>>(x, Wk, bk, kb);
    gemm_xwt<<<gg, 256>>>(x, Wv, bv, vb);

    dim3 ga(S_/128, B_*H_);    // (16, 32)
    attn_kernel<<<ga, 256, SMEM_ATTN>>>(qb, kb, vb, mask, ab);

    gemm_xwt<<<gg, 256>>>(ab, Wo, bo, out);
}

// round 6
// speedup vs baseline: 2.1858x; 1.2524x over previous
#include <cuda_runtime.h>
#include <cuda_bf16.h>
#include <cstdint>
#include <math.h>

#define B_  2
#define S_  2048
#define H_  16
#define DH_ 64
#define D_  1024
#define M_  (B_*S_)   // 4096

// ---------------- scratch (__device__ globals; no allocation allowed) -------
__device__ float g_Q[M_*D_];
__device__ float g_K[M_*D_];
__device__ float g_V[M_*D_];
__device__ float g_A[M_*D_];

__device__ __nv_bfloat16 g_xhi[M_*D_],  g_xlo[M_*D_];
__device__ __nv_bfloat16 g_ahi[M_*D_],  g_alo[M_*D_];
__device__ __nv_bfloat16 g_wqhi[D_*D_], g_wqlo[D_*D_];
__device__ __nv_bfloat16 g_wkhi[D_*D_], g_wklo[D_*D_];
__device__ __nv_bfloat16 g_wvhi[D_*D_], g_wvlo[D_*D_];
__device__ __nv_bfloat16 g_wohi[D_*D_], g_wolo[D_*D_];

// ---------------- helpers ----------------------------------------------------
__device__ __forceinline__ uint32_t smem_u32(const void* p) {
    uint32_t a;
    asm("{ .reg .u64 t; cvta.to.shared.u64 t, %1; cvt.u32.u64 %0, t; }"
        : "=r"(a) : "l"(p));
    return a;
}
__device__ __forceinline__ void cp_async16(uint32_t saddr, const void* gaddr) {
    asm volatile("cp.async.cg.shared.global [%0], [%1], 16;"
                 :: "r"(saddr), "l"(gaddr) : "memory");
}
#define CP_COMMIT() asm volatile("cp.async.commit_group;" ::: "memory")
#define CP_WAIT(n)  asm volatile("cp.async.wait_group %0;" :: "n"(n) : "memory")

__device__ __forceinline__ void ldsm_x4(uint32_t* r, uint32_t addr) {
    asm volatile("ldmatrix.sync.aligned.m8n8.x4.shared.b16 {%0,%1,%2,%3}, [%4];"
                 : "=r"(r[0]), "=r"(r[1]), "=r"(r[2]), "=r"(r[3]) : "r"(addr));
}
__device__ __forceinline__ void mma_bf16(float* c, const uint32_t* a, const uint32_t* b) {
    asm volatile(
        "mma.sync.aligned.m16n8k16.row.col.f32.bf16.bf16.f32 "
        "{%0,%1,%2,%3}, {%4,%5,%6,%7}, {%8,%9}, {%0,%1,%2,%3};"
        : "+f"(c[0]), "+f"(c[1]), "+f"(c[2]), "+f"(c[3])
        : "r"(a[0]), "r"(a[1]), "r"(a[2]), "r"(a[3]), "r"(b[0]), "r"(b[1]));
}

// ---------------- split conversion: f32 -> (bf16 hi, bf16 lo) ---------------
__global__ __launch_bounds__(256) void conv_split(
    const float* __restrict__ x, __nv_bfloat16* __restrict__ hi,
    __nv_bfloat16* __restrict__ lo, int n4)
{
    int i = blockIdx.x * blockDim.x + threadIdx.x;
    if (i >= n4) return;
    float4 v = ((const float4*)x)[i];
    __nv_bfloat16 h0 = __float2bfloat16(v.x);
    __nv_bfloat16 h1 = __float2bfloat16(v.y);
    __nv_bfloat16 h2 = __float2bfloat16(v.z);
    __nv_bfloat16 h3 = __float2bfloat16(v.w);
    __nv_bfloat16 l0 = __float2bfloat16(v.x - __bfloat162float(h0));
    __nv_bfloat16 l1 = __float2bfloat16(v.y - __bfloat162float(h1));
    __nv_bfloat16 l2 = __float2bfloat16(v.z - __bfloat162float(h2));
    __nv_bfloat16 l3 = __float2bfloat16(v.w - __bfloat162float(h3));
    uint2 ho, loo;
    ho.x  = (uint32_t)__bfloat16_as_ushort(h0) | ((uint32_t)__bfloat16_as_ushort(h1) << 16);
    ho.y  = (uint32_t)__bfloat16_as_ushort(h2) | ((uint32_t)__bfloat16_as_ushort(h3) << 16);
    loo.x = (uint32_t)__bfloat16_as_ushort(l0) | ((uint32_t)__bfloat16_as_ushort(l1) << 16);
    loo.y = (uint32_t)__bfloat16_as_ushort(l2) | ((uint32_t)__bfloat16_as_ushort(l3) << 16);
    ((uint2*)hi)[i] = ho;
    ((uint2*)lo)[i] = loo;
}

// ---------------- mma.sync split-bf16 GEMM -----------------------------------
// C[M][N] = A[M][K] @ W[N][K]^T + bias.
// Block 128x128, 8 warps (2m x 4n), warp tile 64x32, BK=32, cp.async double buf.
// C = Ahi*Whi + Ahi*Wlo + Alo*Whi   (fp32 accum).
// A and W are both k-major -> both operands use non-trans ldmatrix.
#define BKH    32                 // k halves per stage
#define PITCH  40                 // smem pitch in halves
#define MAT_B  (128*PITCH*2)      // bytes per matrix per stage (10240)
#define STAGE_B (4*MAT_B)         // Ahi, Alo, Whi, Wlo
#define GEMM_SMEM (2*STAGE_B)     // 81920 bytes

__global__ __launch_bounds__(256, 1) void gemm_mma_split(
    const __nv_bfloat16* __restrict__ Ahi, const __nv_bfloat16* __restrict__ Alo,
    const __nv_bfloat16* __restrict__ Whi, const __nv_bfloat16* __restrict__ Wlo,
    const float* __restrict__ bias, float* __restrict__ C)
{
    extern __shared__ __align__(1024) char smraw[];
    const uint32_t sb = smem_u32(smraw);

    const int tid = threadIdx.x;
    const int wid = tid >> 5;
    const int l   = tid & 31;
    const int wm  = wid & 1;        // 0..1  (m warp)
    const int wn  = wid >> 1;       // 0..3  (n warp)
    const int m0  = blockIdx.y * 128;
    const int n0  = blockIdx.x * 128;

    // global copy mapping: 2 threads per row, each thread owns 16 halves (2x16B)
    const int lrow = tid >> 1;           // 0..127
    const int lcol = (tid & 1) * 16;     // 0 or 16 (halves)
    const __nv_bfloat16* gAh = Ahi + (size_t)(m0 + lrow) * D_ + lcol;
    const __nv_bfloat16* gAl = Alo + (size_t)(m0 + lrow) * D_ + lcol;
    const __nv_bfloat16* gWh = Whi + (size_t)(n0 + lrow) * D_ + lcol;
    const __nv_bfloat16* gWl = Wlo + (size_t)(n0 + lrow) * D_ + lcol;
    const uint32_t sst = (uint32_t)(lrow * PITCH + lcol) * 2;   // byte offset

    // ldmatrix source addresses (byte offsets within one matrix)
    const uint32_t addrA = (uint32_t)((wm*64 + (l & 15)) * PITCH + ((l >> 4) * 8)) * 2;
    const uint32_t addrB = (uint32_t)((wn*32 + (l & 7) + ((l >> 4) << 3)) * PITCH
                                      + (((l >> 3) & 1) * 8)) * 2;

    float acc[4][4][4];
#pragma unroll
    for (int mt = 0; mt < 4; mt++)
#pragma unroll
        for (int nt = 0; nt < 4; nt++)
#pragma unroll
            for (int e = 0; e < 4; e++) acc[mt][nt][e] = 0.f;

    const int NKT = D_ / BKH;   // 32

    // issue one full stage of cp.async copies (32 KB total per stage)
    auto issue_stage = [&](int s) {
        const uint32_t buf = sb + (s & 1) * STAGE_B;
        const int off = s * BKH;
        const uint32_t d0 = buf + sst;
        cp_async16(d0 + 0*MAT_B,      gAh + off);
        cp_async16(d0 + 0*MAT_B + 16, gAh + off + 8);
        cp_async16(d0 + 1*MAT_B,      gAl + off);
        cp_async16(d0 + 1*MAT_B + 16, gAl + off + 8);
        cp_async16(d0 + 2*MAT_B,      gWh + off);
        cp_async16(d0 + 2*MAT_B + 16, gWh + off + 8);
        cp_async16(d0 + 3*MAT_B,      gWl + off);
        cp_async16(d0 + 3*MAT_B + 16, gWl + off + 8);
    };

    issue_stage(0);
    CP_COMMIT();

    for (int kt = 0; kt < NKT; kt++) {
        if (kt + 1 < NKT) {
            issue_stage(kt + 1);
            CP_COMMIT();
            CP_WAIT(1);          // stage kt arrived
        } else {
            CP_WAIT(0);
        }
        __syncthreads();

        const uint32_t base = sb + (kt & 1) * STAGE_B;

#pragma unroll
        for (int kk = 0; kk < 2; kk++) {
            const uint32_t ko = kk * 16 * 2;   // byte offset of k16 step

            uint32_t ah[4][4];
#pragma unroll
            for (int mt = 0; mt < 4; mt++)
                ldsm_x4(ah[mt], base + 0*MAT_B + addrA + mt*(16*PITCH*2) + ko);
            uint32_t wh[2][4];
#pragma unroll
            for (int np = 0; np < 2; np++)
                ldsm_x4(wh[np], base + 2*MAT_B + addrB + np*(16*PITCH*2) + ko);
            // pass 1: Ahi * Whi
#pragma unroll
            for (int mt = 0; mt < 4; mt++)
#pragma unroll
                for (int nt = 0; nt < 4; nt++)
                    mma_bf16(acc[mt][nt], ah[mt], &wh[nt >> 1][(nt & 1) * 2]);

            uint32_t wl[2][4];
#pragma unroll
            for (int np = 0; np < 2; np++)
                ldsm_x4(wl[np], base + 3*MAT_B + addrB + np*(16*PITCH*2) + ko);
            // pass 2: Ahi * Wlo
#pragma unroll
            for (int mt = 0; mt < 4; mt++)
#pragma unroll
                for (int nt = 0; nt < 4; nt++)
                    mma_bf16(acc[mt][nt], ah[mt], &wl[nt >> 1][(nt & 1) * 2]);

            uint32_t al[4][4];
#pragma unroll
            for (int mt = 0; mt < 4; mt++)
                ldsm_x4(al[mt], base + 1*MAT_B + addrA + mt*(16*PITCH*2) + ko);
            // pass 3: Alo * Whi
#pragma unroll
            for (int mt = 0; mt < 4; mt++)
#pragma unroll
                for (int nt = 0; nt < 4; nt++)
                    mma_bf16(acc[mt][nt], al[mt], &wh[nt >> 1][(nt & 1) * 2]);
        }

        __syncthreads();   // all reads of stage kt done before its buffer is reused
    }

    // epilogue: write acc + bias
    const int rbase = m0 + wm*64 + (l >> 2);
    const int cbase = n0 + wn*32 + (l & 3) * 2;
#pragma unroll
    for (int mt = 0; mt < 4; mt++) {
#pragma unroll
        for (int nt = 0; nt < 4; nt++) {
            const int col = cbase + nt * 8;
            const float b0 = bias[col], b1 = bias[col + 1];
            float* p0 = C + (size_t)(rbase + mt*16)     * D_ + col;
            float* p1 = C + (size_t)(rbase + mt*16 + 8) * D_ + col;
            float2 v0 = { acc[mt][nt][0] + b0, acc[mt][nt][1] + b1 };
            float2 v1 = { acc[mt][nt][2] + b0, acc[mt][nt][3] + b1 };
            *(float2*)p0 = v0;
            *(float2*)p1 = v1;
        }
    }
}

// ---------------- fp32 flash attention (R2 version, passing) ----------------
#define QK_PITCH 132
#define V_PITCH  68
#define P_PITCH  132
#define SMEM_ATTN ((64*QK_PITCH*2 + 128*V_PITCH + 128*P_PITCH + 128) * 4)

__global__ __launch_bounds__(256, 1) void attn_kernel(
    const float* __restrict__ Q, const float* __restrict__ K,
    const float* __restrict__ V, const int* __restrict__ mask,
    float* __restrict__ Aout)
{
    extern __shared__ float sm[];
    float* Qst = sm;
    float* Kst = Qst + 64 * QK_PITCH;
    float* Vs  = Kst + 64 * QK_PITCH;
    float* Ps  = Vs  + 128 * V_PITCH;
    float* Msk = Ps  + 128 * P_PITCH;

    const int bh = blockIdx.y;
    const int b  = bh / H_;
    const int h  = bh % H_;
    const int q0 = blockIdx.x * 128;

    const int tid = threadIdx.x;
    const int tx  = tid & 15;
    const int ty  = tid >> 4;

    {
        const float* Qb = Q + ((size_t)(b*S_ + q0)) * D_ + h*DH_;
#pragma unroll
        for (int it = 0; it < 8; it++) {
            int f  = tid + it * 256;
            int qr = f >> 4;
            int dq = (f & 15) * 4;
            float4 v = *(const float4*)(Qb + (size_t)qr * D_ + dq);
            Qst[(dq+0)*QK_PITCH + qr] = v.x;
            Qst[(dq+1)*QK_PITCH + qr] = v.y;
            Qst[(dq+2)*QK_PITCH + qr] = v.z;
            Qst[(dq+3)*QK_PITCH + qr] = v.w;
        }
    }

    const float scale = 0.125f;
    float m_run[8], l_run[8], o[8][4];
#pragma unroll
    for (int i = 0; i < 8; i++) {
        m_run[i] = -1e30f; l_run[i] = 0.f;
#pragma unroll
        for (int j = 0; j < 4; j++) o[i][j] = 0.f;
    }

    const float* Kb0 = K + ((size_t)b*S_) * D_ + h*DH_;
    const float* Vb0 = V + ((size_t)b*S_) * D_ + h*DH_;

    for (int kt = 0; kt < S_; kt += 128) {
        __syncthreads();
        {
            const float* Kb = Kb0 + (size_t)kt * D_;
            const float* Vb = Vb0 + (size_t)kt * D_;
#pragma unroll
            for (int it = 0; it < 8; it++) {
                int f  = tid + it * 256;
                int kr = f >> 4;
                int dq = (f & 15) * 4;
                float4 kv = *(const float4*)(Kb + (size_t)kr * D_ + dq);
                float4 vv = *(const float4*)(Vb + (size_t)kr * D_ + dq);
                Kst[(dq+0)*QK_PITCH + kr] = kv.x;
                Kst[(dq+1)*QK_PITCH + kr] = kv.y;
                Kst[(dq+2)*QK_PITCH + kr] = kv.z;
                Kst[(dq+3)*QK_PITCH + kr] = kv.w;
                Vs[kr*V_PITCH + dq + 0] = vv.x;
                Vs[kr*V_PITCH + dq + 1] = vv.y;
                Vs[kr*V_PITCH + dq + 2] = vv.z;
                Vs[kr*V_PITCH + dq + 3] = vv.w;
            }
            if (tid < 128) Msk[tid] = (float)mask[(size_t)b*S_ + kt + tid];
        }
        __syncthreads();

        float s[8][8];
#pragma unroll
        for (int i = 0; i < 8; i++)
#pragma unroll
            for (int j = 0; j < 8; j++) s[i][j] = 0.f;

#pragma unroll 4
        for (int d = 0; d < 64; d++) {
            float a[8], bb[8];
            *(float4*)(a)      = *(const float4*)&Qst[d*QK_PITCH + ty*8];
            *(float4*)(a + 4)  = *(const float4*)&Qst[d*QK_PITCH + ty*8 + 4];
            *(float4*)(bb)     = *(const float4*)&Kst[d*QK_PITCH + tx*8];
            *(float4*)(bb + 4) = *(const float4*)&Kst[d*QK_PITCH + tx*8 + 4];
#pragma unroll
            for (int i = 0; i < 8; i++)
#pragma unroll
                for (int j = 0; j < 8; j++) s[i][j] += a[i] * bb[j];
        }

        float mk[8];
#pragma unroll
        for (int j = 0; j < 8; j++) mk[j] = Msk[tx*8 + j];

        float mt[8];
#pragma unroll
        for (int i = 0; i < 8; i++) {
            float rm = -1e30f;
#pragma unroll
            for (int j = 0; j < 8; j++) {
                float sc = s[i][j] * scale;
                sc = (mk[j] != 0.f) ? sc : -1e30f;
                s[i][j] = sc;
                rm = fmaxf(rm, sc);
            }
            mt[i] = rm;
        }
#pragma unroll
        for (int i = 0; i < 8; i++) {
            float v = mt[i];
            v = fmaxf(v, __shfl_xor_sync(0xffffffffu, v, 1));
            v = fmaxf(v, __shfl_xor_sync(0xffffffffu, v, 2));
            v = fmaxf(v, __shfl_xor_sync(0xffffffffu, v, 4));
            v = fmaxf(v, __shfl_xor_sync(0xffffffffu, v, 8));
            mt[i] = v;
        }

        float alpha[8], rs[8];
#pragma unroll
        for (int i = 0; i < 8; i++) {
            float mnew = fmaxf(m_run[i], mt[i]);
            alpha[i]   = __expf(m_run[i] - mnew);
            m_run[i]   = mnew;
            float acc = 0.f;
#pragma unroll
            for (int j = 0; j < 8; j++) {
                float p = __expf(s[i][j] - mnew);
                s[i][j] = p;
                acc += p;
            }
            rs[i] = acc;
        }
#pragma unroll
        for (int i = 0; i < 8; i++) {
            float v = rs[i];
            v += __shfl_xor_sync(0xffffffffu, v, 1);
            v += __shfl_xor_sync(0xffffffffu, v, 2);
            v += __shfl_xor_sync(0xffffffffu, v, 4);
            v += __shfl_xor_sync(0xffffffffu, v, 8);
            l_run[i] = l_run[i] * alpha[i] + v;
        }

#pragma unroll
        for (int i = 0; i < 8; i++) {
#pragma unroll
            for (int j = 0; j < 4; j++) o[i][j] *= alpha[i];
            *(float4*)&Ps[(ty*8+i)*P_PITCH + tx*8]     = *(float4*)&s[i][0];
            *(float4*)&Ps[(ty*8+i)*P_PITCH + tx*8 + 4] = *(float4*)&s[i][4];
        }
        __syncthreads();

#pragma unroll 2
        for (int c = 0; c < 128; c++) {
            float4 vb = *(const float4*)&Vs[c*V_PITCH + tx*4];
#pragma unroll
            for (int i = 0; i < 8; i++) {
                float p = Ps[(ty*8+i)*P_PITCH + c];
                o[i][0] += p * vb.x;
                o[i][1] += p * vb.y;
                o[i][2] += p * vb.z;
                o[i][3] += p * vb.w;
            }
        }
    }

#pragma unroll
    for (int i = 0; i < 8; i++) {
        float inv = 1.f / l_run[i];
        float4 r;
        r.x = o[i][0]*inv; r.y = o[i][1]*inv; r.z = o[i][2]*inv; r.w = o[i][3]*inv;
        float* dst = Aout + ((size_t)(b*S_ + q0 + ty*8 + i)) * D_ + h*DH_ + tx*4;
        *(float4*)dst = r;
    }
}

// ---------------------------------------------------------------------------
extern "C" void kernel_launch(void* const* d_in, const int* in_sizes, int n_in,
                              void* d_out, int out_size)
{
    const float* x    = (const float*)d_in[0];
    const int*   mask = (const int*)  d_in[1];
    const float* Wq   = (const float*)d_in[2];
    const float* bq   = (const float*)d_in[3];
    const float* Wk   = (const float*)d_in[4];
    const float* bk   = (const float*)d_in[5];
    const float* Wv   = (const float*)d_in[6];
    const float* bv   = (const float*)d_in[7];
    const float* Wo   = (const float*)d_in[8];
    const float* bo   = (const float*)d_in[9];
    float* out = (float*)d_out;

    float *qb, *kb, *vb, *ab;
    cudaGetSymbolAddress((void**)&qb, g_Q);
    cudaGetSymbolAddress((void**)&kb, g_K);
    cudaGetSymbolAddress((void**)&vb, g_V);
    cudaGetSymbolAddress((void**)&ab, g_A);

    __nv_bfloat16 *xhi, *xlo, *ahi, *alo;
    __nv_bfloat16 *wqh, *wql, *wkh, *wkl, *wvh, *wvl, *woh, *wol;
    cudaGetSymbolAddress((void**)&xhi, g_xhi);
    cudaGetSymbolAddress((void**)&xlo, g_xlo);
    cudaGetSymbolAddress((void**)&ahi, g_ahi);
    cudaGetSymbolAddress((void**)&alo, g_alo);
    cudaGetSymbolAddress((void**)&wqh, g_wqhi);
    cudaGetSymbolAddress((void**)&wql, g_wqlo);
    cudaGetSymbolAddress((void**)&wkh, g_wkhi);
    cudaGetSymbolAddress((void**)&wkl, g_wklo);
    cudaGetSymbolAddress((void**)&wvh, g_wvhi);
    cudaGetSymbolAddress((void**)&wvl, g_wvlo);
    cudaGetSymbolAddress((void**)&woh, g_wohi);
    cudaGetSymbolAddress((void**)&wol, g_wolo);

    cudaFuncSetAttribute(gemm_mma_split,
                         cudaFuncAttributeMaxDynamicSharedMemorySize, GEMM_SMEM);
    cudaFuncSetAttribute(attn_kernel,
                         cudaFuncAttributeMaxDynamicSharedMemorySize, SMEM_ATTN);

    conv_split<<<(M_*D_/4)/256, 256>>>(x,  xhi, xlo, M_*D_/4);
    conv_split<<<(D_*D_/4)/256, 256>>>(Wq, wqh, wql, D_*D_/4);
    conv_split<<<(D_*D_/4)/256, 256>>>(Wk, wkh, wkl, D_*D_/4);
    conv_split<<<(D_*D_/4)/256, 256>>>(Wv, wvh, wvl, D_*D_/4);
    conv_split<<<(D_*D_/4)/256, 256>>>(Wo, woh, wol, D_*D_/4);

    dim3 gg(D_/128, M_/128);   // (8, 32)
    gemm_mma_split<<<gg, 256, GEMM_SMEM>>>(xhi, xlo, wqh, wql, bq, qb);
    gemm_mma_split<<<gg, 256, GEMM_SMEM>>>(xhi, xlo, wkh, wkl, bk, kb);
    gemm_mma_split<<<gg, 256, GEMM_SMEM>>>(xhi, xlo, wvh, wvl, bv, vb);

    dim3 ga(S_/128, B_*H_);    // (16, 32)
    attn_kernel<<<ga, 256, SMEM_ATTN>>>(qb, kb, vb, mask, ab);

    conv_split<<<(M_*D_/4)/256, 256>>>(ab, ahi, alo, M_*D_/4);
    gemm_mma_split<<<gg, 256, GEMM_SMEM>>>(ahi, alo, woh, wol, bo, out);
}

// round 7
// speedup vs baseline: 3.5998x; 1.6469x over previous
#include <cuda_runtime.h>
#include <cuda_bf16.h>
#include <cstdint>
#include <math.h>

#define B_  2
#define S_  2048
#define H_  16
#define DH_ 64
#define D_  1024
#define M_  (B_*S_)   // 4096

// ---------------- scratch (__device__ globals; no allocation allowed) -------
__device__ __nv_bfloat16 g_xhi[M_*D_],  g_xlo[M_*D_];
__device__ __nv_bfloat16 g_qhi[M_*D_],  g_qlo[M_*D_];
__device__ __nv_bfloat16 g_khi[M_*D_],  g_klo[M_*D_];
__device__ __nv_bfloat16 g_vhi[M_*D_],  g_vlo[M_*D_];
__device__ __nv_bfloat16 g_ahi[M_*D_],  g_alo[M_*D_];
__device__ __nv_bfloat16 g_wqhi[D_*D_], g_wqlo[D_*D_];
__device__ __nv_bfloat16 g_wkhi[D_*D_], g_wklo[D_*D_];
__device__ __nv_bfloat16 g_wvhi[D_*D_], g_wvlo[D_*D_];
__device__ __nv_bfloat16 g_wohi[D_*D_], g_wolo[D_*D_];

// ---------------- helpers ----------------------------------------------------
__device__ __forceinline__ uint32_t smem_u32(const void* p) {
    uint32_t a;
    asm("{ .reg .u64 t; cvta.to.shared.u64 t, %1; cvt.u32.u64 %0, t; }"
        : "=r"(a) : "l"(p));
    return a;
}
__device__ __forceinline__ void cp_async16(uint32_t saddr, const void* gaddr) {
    asm volatile("cp.async.cg.shared.global [%0], [%1], 16;"
                 :: "r"(saddr), "l"(gaddr) : "memory");
}
#define CP_COMMIT() asm volatile("cp.async.commit_group;" ::: "memory")
#define CP_WAIT(n)  asm volatile("cp.async.wait_group %0;" :: "n"(n) : "memory")

__device__ __forceinline__ void ldsm_x4(uint32_t* r, uint32_t addr) {
    asm volatile("ldmatrix.sync.aligned.m8n8.x4.shared.b16 {%0,%1,%2,%3}, [%4];"
                 : "=r"(r[0]), "=r"(r[1]), "=r"(r[2]), "=r"(r[3]) : "r"(addr));
}
__device__ __forceinline__ void ldsm_x4t(uint32_t* r, uint32_t addr) {
    asm volatile("ldmatrix.sync.aligned.m8n8.x4.trans.shared.b16 {%0,%1,%2,%3}, [%4];"
                 : "=r"(r[0]), "=r"(r[1]), "=r"(r[2]), "=r"(r[3]) : "r"(addr));
}
__device__ __forceinline__ void mma_bf16(float* c, const uint32_t* a, const uint32_t* b) {
    asm volatile(
        "mma.sync.aligned.m16n8k16.row.col.f32.bf16.bf16.f32 "
        "{%0,%1,%2,%3}, {%4,%5,%6,%7}, {%8,%9}, {%0,%1,%2,%3};"
        : "+f"(c[0]), "+f"(c[1]), "+f"(c[2]), "+f"(c[3])
        : "r"(a[0]), "r"(a[1]), "r"(a[2]), "r"(a[3]), "r"(b[0]), "r"(b[1]));
}
// pack two floats into bf16x2 hi + bf16x2 lo words
__device__ __forceinline__ void split2(float x0, float x1, uint32_t& hi, uint32_t& lo) {
    __nv_bfloat16 h0 = __float2bfloat16(x0);
    __nv_bfloat16 h1 = __float2bfloat16(x1);
    __nv_bfloat16 l0 = __float2bfloat16(x0 - __bfloat162float(h0));
    __nv_bfloat16 l1 = __float2bfloat16(x1 - __bfloat162float(h1));
    hi = (uint32_t)__bfloat16_as_ushort(h0) | ((uint32_t)__bfloat16_as_ushort(h1) << 16);
    lo = (uint32_t)__bfloat16_as_ushort(l0) | ((uint32_t)__bfloat16_as_ushort(l1) << 16);
}

// ---------------- split conversion: f32 -> (bf16 hi, bf16 lo) ---------------
__global__ __launch_bounds__(256) void conv_split(
    const float* __restrict__ x, __nv_bfloat16* __restrict__ hi,
    __nv_bfloat16* __restrict__ lo, int n4)
{
    int i = blockIdx.x * blockDim.x + threadIdx.x;
    if (i >= n4) return;
    float4 v = ((const float4*)x)[i];
    uint32_t h0, l0, h1, l1;
    split2(v.x, v.y, h0, l0);
    split2(v.z, v.w, h1, l1);
    uint2 ho = { h0, h1 }, loo = { l0, l1 };
    ((uint2*)hi)[i] = ho;
    ((uint2*)lo)[i] = loo;
}

// ---------------- mma.sync split-bf16 GEMM -----------------------------------
// C[M][N] = A[M][K] @ W[N][K]^T + bias.  SPLIT=1: write bf16 hi/lo instead of f32.
#define BKH    32
#define PITCH  40
#define MAT_B  (128*PITCH*2)
#define STAGE_B (4*MAT_B)
#define GEMM_SMEM (2*STAGE_B)

template <bool SPLIT>
__global__ __launch_bounds__(256, 1) void gemm_mma_split(
    const __nv_bfloat16* __restrict__ Ahi, const __nv_bfloat16* __restrict__ Alo,
    const __nv_bfloat16* __restrict__ Whi, const __nv_bfloat16* __restrict__ Wlo,
    const float* __restrict__ bias, float* __restrict__ C,
    __nv_bfloat16* __restrict__ Chi, __nv_bfloat16* __restrict__ Clo)
{
    extern __shared__ __align__(1024) char smraw[];
    const uint32_t sb = smem_u32(smraw);

    const int tid = threadIdx.x;
    const int wid = tid >> 5;
    const int l   = tid & 31;
    const int wm  = wid & 1;
    const int wn  = wid >> 1;
    const int m0  = blockIdx.y * 128;
    const int n0  = blockIdx.x * 128;

    const int lrow = tid >> 1;
    const int lcol = (tid & 1) * 16;
    const __nv_bfloat16* gAh = Ahi + (size_t)(m0 + lrow) * D_ + lcol;
    const __nv_bfloat16* gAl = Alo + (size_t)(m0 + lrow) * D_ + lcol;
    const __nv_bfloat16* gWh = Whi + (size_t)(n0 + lrow) * D_ + lcol;
    const __nv_bfloat16* gWl = Wlo + (size_t)(n0 + lrow) * D_ + lcol;
    const uint32_t sst = (uint32_t)(lrow * PITCH + lcol) * 2;

    const uint32_t addrA = (uint32_t)((wm*64 + (l & 15)) * PITCH + ((l >> 4) * 8)) * 2;
    const uint32_t addrB = (uint32_t)((wn*32 + (l & 7) + ((l >> 4) << 3)) * PITCH
                                      + (((l >> 3) & 1) * 8)) * 2;

    float acc[4][4][4];
#pragma unroll
    for (int mt = 0; mt < 4; mt++)
#pragma unroll
        for (int nt = 0; nt < 4; nt++)
#pragma unroll
            for (int e = 0; e < 4; e++) acc[mt][nt][e] = 0.f;

    const int NKT = D_ / BKH;

    auto issue_stage = [&](int s) {
        const uint32_t buf = sb + (s & 1) * STAGE_B;
        const int off = s * BKH;
        const uint32_t d0 = buf + sst;
        cp_async16(d0 + 0*MAT_B,      gAh + off);
        cp_async16(d0 + 0*MAT_B + 16, gAh + off + 8);
        cp_async16(d0 + 1*MAT_B,      gAl + off);
        cp_async16(d0 + 1*MAT_B + 16, gAl + off + 8);
        cp_async16(d0 + 2*MAT_B,      gWh + off);
        cp_async16(d0 + 2*MAT_B + 16, gWh + off + 8);
        cp_async16(d0 + 3*MAT_B,      gWl + off);
        cp_async16(d0 + 3*MAT_B + 16, gWl + off + 8);
    };

    issue_stage(0);
    CP_COMMIT();

    for (int kt = 0; kt < NKT; kt++) {
        if (kt + 1 < NKT) {
            issue_stage(kt + 1);
            CP_COMMIT();
            CP_WAIT(1);
        } else {
            CP_WAIT(0);
        }
        __syncthreads();

        const uint32_t base = sb + (kt & 1) * STAGE_B;

#pragma unroll
        for (int kk = 0; kk < 2; kk++) {
            const uint32_t ko = kk * 32;

            uint32_t ah[4][4];
#pragma unroll
            for (int mt = 0; mt < 4; mt++)
                ldsm_x4(ah[mt], base + 0*MAT_B + addrA + mt*(16*PITCH*2) + ko);
            uint32_t wh[2][4];
#pragma unroll
            for (int np = 0; np < 2; np++)
                ldsm_x4(wh[np], base + 2*MAT_B + addrB + np*(16*PITCH*2) + ko);
#pragma unroll
            for (int mt = 0; mt < 4; mt++)
#pragma unroll
                for (int nt = 0; nt < 4; nt++)
                    mma_bf16(acc[mt][nt], ah[mt], &wh[nt >> 1][(nt & 1) * 2]);

            uint32_t wl[2][4];
#pragma unroll
            for (int np = 0; np < 2; np++)
                ldsm_x4(wl[np], base + 3*MAT_B + addrB + np*(16*PITCH*2) + ko);
#pragma unroll
            for (int mt = 0; mt < 4; mt++)
#pragma unroll
                for (int nt = 0; nt < 4; nt++)
                    mma_bf16(acc[mt][nt], ah[mt], &wl[nt >> 1][(nt & 1) * 2]);

            uint32_t al[4][4];
#pragma unroll
            for (int mt = 0; mt < 4; mt++)
                ldsm_x4(al[mt], base + 1*MAT_B + addrA + mt*(16*PITCH*2) + ko);
#pragma unroll
            for (int mt = 0; mt < 4; mt++)
#pragma unroll
                for (int nt = 0; nt < 4; nt++)
                    mma_bf16(acc[mt][nt], al[mt], &wh[nt >> 1][(nt & 1) * 2]);
        }

        __syncthreads();
    }

    const int rbase = m0 + wm*64 + (l >> 2);
    const int cbase = n0 + wn*32 + (l & 3) * 2;
#pragma unroll
    for (int mt = 0; mt < 4; mt++) {
#pragma unroll
        for (int nt = 0; nt < 4; nt++) {
            const int col = cbase + nt * 8;
            const float b0 = bias[col], b1 = bias[col + 1];
            const size_t r0o = (size_t)(rbase + mt*16) * D_ + col;
            const size_t r1o = (size_t)(rbase + mt*16 + 8) * D_ + col;
            if (SPLIT) {
                uint32_t hi, lo;
                split2(acc[mt][nt][0] + b0, acc[mt][nt][1] + b1, hi, lo);
                *(uint32_t*)(Chi + r0o) = hi;
                *(uint32_t*)(Clo + r0o) = lo;
                split2(acc[mt][nt][2] + b0, acc[mt][nt][3] + b1, hi, lo);
                *(uint32_t*)(Chi + r1o) = hi;
                *(uint32_t*)(Clo + r1o) = lo;
            } else {
                float2 v0 = { acc[mt][nt][0] + b0, acc[mt][nt][1] + b1 };
                float2 v1 = { acc[mt][nt][2] + b0, acc[mt][nt][3] + b1 };
                *(float2*)(C + r0o) = v0;
                *(float2*)(C + r1o) = v1;
            }
        }
    }
}

// ---------------- mma.sync split-bf16 flash attention ------------------------
// CTA: 128 queries, 8 warps x 16 q-rows (full 128-key tiles in-warp).
// QK^T: 3-pass split; P split hi/lo via smem; PV: 3-pass split, V via ldmatrix.trans.
#define AT_QP 72     // Q/K/V smem pitch (halves); 144B rows, conflict-free
#define AT_PP 136    // P smem pitch (halves); 272B rows
#define oQh 0
#define oQl 18432
#define oKh 36864
#define oKl 55296
#define oVh 73728
#define oVl 92160
#define oPh 110592
#define oPl 145408
#define oMs 180224
#define ATT_SMEM (oMs + S_*4)    // 188416

__global__ __launch_bounds__(256, 1) void attn_mma(
    const __nv_bfloat16* __restrict__ Qh, const __nv_bfloat16* __restrict__ Ql,
    const __nv_bfloat16* __restrict__ Kh, const __nv_bfloat16* __restrict__ Kl,
    const __nv_bfloat16* __restrict__ Vh, const __nv_bfloat16* __restrict__ Vl,
    const int* __restrict__ mask,
    __nv_bfloat16* __restrict__ Ah, __nv_bfloat16* __restrict__ Al)
{
    extern __shared__ __align__(1024) char sm[];
    const uint32_t sb = smem_u32(sm);
    float* Mskf = (float*)(sm + oMs);

    const int tid = threadIdx.x;
    const int wid = tid >> 5;
    const int l   = tid & 31;
    const int b   = blockIdx.y >> 4;
    const int h   = blockIdx.y & 15;
    const int q0  = blockIdx.x * 128;

    // mask -> smem (full sequence for this batch)
    for (int i = tid; i < S_; i += 256)
        Mskf[i] = (float)mask[(size_t)b*S_ + i];

    // Q tiles (hi/lo), cp.async: row = tid>>1, halfcol = (tid&1)*32
    {
        const int row = tid >> 1, hc = (tid & 1) * 32;
        const size_t g = (size_t)(b*S_ + q0 + row) * D_ + h*DH_ + hc;
        const uint32_t ds = (uint32_t)(row * AT_QP + hc) * 2;
#pragma unroll
        for (int j = 0; j < 4; j++) {
            cp_async16(sb + oQh + ds + j*16, Qh + g + j*8);
            cp_async16(sb + oQl + ds + j*16, Ql + g + j*8);
        }
    }
    CP_COMMIT();

    float m_run[2] = { -1e30f, -1e30f };
    float l_run[2] = { 0.f, 0.f };
    float o[8][4];
#pragma unroll
    for (int nt = 0; nt < 8; nt++)
#pragma unroll
        for (int e = 0; e < 4; e++) o[nt][e] = 0.f;

    const uint32_t aQh = sb + oQh + (uint32_t)(((wid<<4) + (l & 15)) * AT_QP + ((l >> 4) << 3)) * 2;
    const uint32_t aQl = aQh + (oQl - oQh);
    const uint32_t aKo = (uint32_t)(((l & 7) + ((l >> 4) << 3)) * AT_QP + (((l >> 3) & 1) << 3)) * 2;
    const uint32_t aPh = sb + oPh + (uint32_t)(((wid<<4) + (l & 15)) * AT_PP + ((l >> 4) << 3)) * 2;
    const uint32_t aPl = aPh + (oPl - oPh);
    const uint32_t aVo = (uint32_t)(((l & 7) + (((l >> 3) & 1) << 3)) * AT_QP + ((l >> 4) << 3)) * 2;

    const int r0 = l >> 2;
    const int c0 = (l & 3) * 2;

    for (int kt = 0; kt < S_/128; kt++) {
        __syncthreads();   // previous iter's P/V reads complete
        // K/V tiles (hi/lo)
        {
            const int row = tid >> 1, hc = (tid & 1) * 32;
            const size_t g = (size_t)(b*S_ + kt*128 + row) * D_ + h*DH_ + hc;
            const uint32_t ds = (uint32_t)(row * AT_QP + hc) * 2;
#pragma unroll
            for (int j = 0; j < 4; j++) {
                cp_async16(sb + oKh + ds + j*16, Kh + g + j*8);
                cp_async16(sb + oKl + ds + j*16, Kl + g + j*8);
                cp_async16(sb + oVh + ds + j*16, Vh + g + j*8);
                cp_async16(sb + oVl + ds + j*16, Vl + g + j*8);
            }
        }
        CP_COMMIT(); CP_WAIT(0);
        __syncthreads();

        // ---- QK^T: scores s[16 n-groups][4] ----
        float s[16][4];
#pragma unroll
        for (int nt = 0; nt < 16; nt++)
#pragma unroll
            for (int e = 0; e < 4; e++) s[nt][e] = 0.f;

#pragma unroll
        for (int ks = 0; ks < 4; ks++) {
            uint32_t qh[4], ql[4];
            ldsm_x4(qh, aQh + ks*32);
            ldsm_x4(ql, aQl + ks*32);
#pragma unroll
            for (int np = 0; np < 8; np++) {
                const uint32_t ka = sb + aKo + np*(16*AT_QP*2) + ks*32;
                uint32_t kh[4], kl[4];
                ldsm_x4(kh, ka + oKh);
                ldsm_x4(kl, ka + oKl);
                mma_bf16(s[2*np],   qh, kh);     mma_bf16(s[2*np+1], qh, kh+2);
                mma_bf16(s[2*np],   qh, kl);     mma_bf16(s[2*np+1], qh, kl+2);
                mma_bf16(s[2*np],   ql, kh);     mma_bf16(s[2*np+1], ql, kh+2);
            }
        }

        // ---- mask + scale + online softmax (rows r0, r0+8 in-warp) ----
        const int kb = kt * 128;
        float mx0 = -1e30f, mx1 = -1e30f;
#pragma unroll
        for (int nt = 0; nt < 16; nt++) {
            const float k0 = Mskf[kb + nt*8 + c0];
            const float k1 = Mskf[kb + nt*8 + c0 + 1];
            s[nt][0] = (k0 != 0.f) ? s[nt][0] * 0.125f : -1e30f;
            s[nt][1] = (k1 != 0.f) ? s[nt][1] * 0.125f : -1e30f;
            s[nt][2] = (k0 != 0.f) ? s[nt][2] * 0.125f : -1e30f;
            s[nt][3] = (k1 != 0.f) ? s[nt][3] * 0.125f : -1e30f;
            mx0 = fmaxf(mx0, fmaxf(s[nt][0], s[nt][1]));
            mx1 = fmaxf(mx1, fmaxf(s[nt][2], s[nt][3]));
        }
        mx0 = fmaxf(mx0, __shfl_xor_sync(0xffffffffu, mx0, 1));
        mx0 = fmaxf(mx0, __shfl_xor_sync(0xffffffffu, mx0, 2));
        mx1 = fmaxf(mx1, __shfl_xor_sync(0xffffffffu, mx1, 1));
        mx1 = fmaxf(mx1, __shfl_xor_sync(0xffffffffu, mx1, 2));

        const float mn0 = fmaxf(m_run[0], mx0);
        const float mn1 = fmaxf(m_run[1], mx1);
        const float al0 = __expf(m_run[0] - mn0);
        const float al1 = __expf(m_run[1] - mn1);
        m_run[0] = mn0; m_run[1] = mn1;

        float su0 = 0.f, su1 = 0.f;
#pragma unroll
        for (int nt = 0; nt < 16; nt++) {
            s[nt][0] = __expf(s[nt][0] - mn0);
            s[nt][1] = __expf(s[nt][1] - mn0);
            s[nt][2] = __expf(s[nt][2] - mn1);
            s[nt][3] = __expf(s[nt][3] - mn1);
            su0 += s[nt][0] + s[nt][1];
            su1 += s[nt][2] + s[nt][3];
        }
        su0 += __shfl_xor_sync(0xffffffffu, su0, 1);
        su0 += __shfl_xor_sync(0xffffffffu, su0, 2);
        su1 += __shfl_xor_sync(0xffffffffu, su1, 1);
        su1 += __shfl_xor_sync(0xffffffffu, su1, 2);
        l_run[0] = l_run[0] * al0 + su0;
        l_run[1] = l_run[1] * al1 + su1;

#pragma unroll
        for (int nt = 0; nt < 8; nt++) {
            o[nt][0] *= al0; o[nt][1] *= al0;
            o[nt][2] *= al1; o[nt][3] *= al1;
        }

        // ---- store P hi/lo to smem ----
        {
            char* p0 = sm + oPh + (size_t)(((wid<<4) + r0) * AT_PP + c0) * 2;
            char* p1 = p0 + 8 * AT_PP * 2;
            const ptrdiff_t dlo = oPl - oPh;
#pragma unroll
            for (int nt = 0; nt < 16; nt++) {
                uint32_t hi, lo;
                split2(s[nt][0], s[nt][1], hi, lo);
                *(uint32_t*)(p0 + nt*16)       = hi;
                *(uint32_t*)(p0 + nt*16 + dlo) = lo;
                split2(s[nt][2], s[nt][3], hi, lo);
                *(uint32_t*)(p1 + nt*16)       = hi;
                *(uint32_t*)(p1 + nt*16 + dlo) = lo;
            }
        }
        __syncthreads();   // P visible to all warps

        // ---- PV: o += P @ V ----
#pragma unroll
        for (int ks = 0; ks < 8; ks++) {
            uint32_t ph[4], pl[4];
            ldsm_x4(ph, aPh + ks*32);
            ldsm_x4(pl, aPl + ks*32);
#pragma unroll
            for (int vb = 0; vb < 4; vb++) {
                const uint32_t va = sb + aVo + ks*(16*AT_QP*2) + vb*32;
                uint32_t vh[4], vl[4];
                ldsm_x4t(vh, va + oVh);
                ldsm_x4t(vl, va + oVl);
                mma_bf16(o[2*vb],   ph, vh);     mma_bf16(o[2*vb+1], ph, vh+2);
                mma_bf16(o[2*vb],   ph, vl);     mma_bf16(o[2*vb+1], ph, vl+2);
                mma_bf16(o[2*vb],   pl, vh);     mma_bf16(o[2*vb+1], pl, vh+2);
            }
        }
    }

    // ---- epilogue: normalize, split to bf16 hi/lo, write ----
    const float i0 = 1.f / l_run[0];
    const float i1 = 1.f / l_run[1];
    const size_t row0 = (size_t)(b*S_ + q0 + (wid<<4) + r0);
    const size_t row1 = row0 + 8;
#pragma unroll
    for (int nt = 0; nt < 8; nt++) {
        const int col = h*DH_ + nt*8 + c0;
        uint32_t hi, lo;
        split2(o[nt][0]*i0, o[nt][1]*i0, hi, lo);
        *(uint32_t*)(Ah + row0*D_ + col) = hi;
        *(uint32_t*)(Al + row0*D_ + col) = lo;
        split2(o[nt][2]*i1, o[nt][3]*i1, hi, lo);
        *(uint32_t*)(Ah + row1*D_ + col) = hi;
        *(uint32_t*)(Al + row1*D_ + col) = lo;
    }
}

// ---------------------------------------------------------------------------
extern "C" void kernel_launch(void* const* d_in, const int* in_sizes, int n_in,
                              void* d_out, int out_size)
{
    const float* x    = (const float*)d_in[0];
    const int*   mask = (const int*)  d_in[1];
    const float* Wq   = (const float*)d_in[2];
    const float* bq   = (const float*)d_in[3];
    const float* Wk   = (const float*)d_in[4];
    const float* bk   = (const float*)d_in[5];
    const float* Wv   = (const float*)d_in[6];
    const float* bv   = (const float*)d_in[7];
    const float* Wo   = (const float*)d_in[8];
    const float* bo   = (const float*)d_in[9];
    float* out = (float*)d_out;

    __nv_bfloat16 *xhi, *xlo, *qhi, *qlo, *khi, *klo, *vhi, *vlo, *ahi, *alo;
    __nv_bfloat16 *wqh, *wql, *wkh, *wkl, *wvh, *wvl, *woh, *wol;
    cudaGetSymbolAddress((void**)&xhi, g_xhi);
    cudaGetSymbolAddress((void**)&xlo, g_xlo);
    cudaGetSymbolAddress((void**)&qhi, g_qhi);
    cudaGetSymbolAddress((void**)&qlo, g_qlo);
    cudaGetSymbolAddress((void**)&khi, g_khi);
    cudaGetSymbolAddress((void**)&klo, g_klo);
    cudaGetSymbolAddress((void**)&vhi, g_vhi);
    cudaGetSymbolAddress((void**)&vlo, g_vlo);
    cudaGetSymbolAddress((void**)&ahi, g_ahi);
    cudaGetSymbolAddress((void**)&alo, g_alo);
    cudaGetSymbolAddress((void**)&wqh, g_wqhi);
    cudaGetSymbolAddress((void**)&wql, g_wqlo);
    cudaGetSymbolAddress((void**)&wkh, g_wkhi);
    cudaGetSymbolAddress((void**)&wkl, g_wklo);
    cudaGetSymbolAddress((void**)&wvh, g_wvhi);
    cudaGetSymbolAddress((void**)&wvl, g_wvlo);
    cudaGetSymbolAddress((void**)&woh, g_wohi);
    cudaGetSymbolAddress((void**)&wol, g_wolo);

    cudaFuncSetAttribute(gemm_mma_split<true>,
                         cudaFuncAttributeMaxDynamicSharedMemorySize, GEMM_SMEM);
    cudaFuncSetAttribute(gemm_mma_split<false>,
                         cudaFuncAttributeMaxDynamicSharedMemorySize, GEMM_SMEM);
    cudaFuncSetAttribute(attn_mma,
                         cudaFuncAttributeMaxDynamicSharedMemorySize, ATT_SMEM);

    conv_split<<<(M_*D_/4)/256, 256>>>(x,  xhi, xlo, M_*D_/4);
    conv_split<<<(D_*D_/4)/256, 256>>>(Wq, wqh, wql, D_*D_/4);
    conv_split<<<(D_*D_/4)/256, 256>>>(Wk, wkh, wkl, D_*D_/4);
    conv_split<<<(D_*D_/4)/256, 256>>>(Wv, wvh, wvl, D_*D_/4);
    conv_split<<<(D_*D_/4)/256, 256>>>(Wo, woh, wol, D_*D_/4);

    dim3 gg(D_/128, M_/128);   // (8, 32)
    gemm_mma_split<true><<<gg, 256, GEMM_SMEM>>>(xhi, xlo, wqh, wql, bq, nullptr, qhi, qlo);
    gemm_mma_split<true><<<gg, 256, GEMM_SMEM>>>(xhi, xlo, wkh, wkl, bk, nullptr, khi, klo);
    gemm_mma_split<true><<<gg, 256, GEMM_SMEM>>>(xhi, xlo, wvh, wvl, bv, nullptr, vhi, vlo);

    dim3 ga(S_/128, B_*H_);    // (16, 32)
    attn_mma<<<ga, 256, ATT_SMEM>>>(qhi, qlo, khi, klo, vhi, vlo, mask, ahi, alo);

    gemm_mma_split<false><<<gg, 256, GEMM_SMEM>>>(ahi, alo, woh, wol, bo, out, nullptr, nullptr);
}

// round 8
// speedup vs baseline: 4.1403x; 1.1502x over previous
#include <cuda_runtime.h>
#include <cuda_bf16.h>
#include <cstdint>
#include <math.h>

#define B_  2
#define S_  2048
#define H_  16
#define DH_ 64
#define D_  1024
#define M_  (B_*S_)   // 4096

// ---------------- scratch (__device__ globals; no allocation allowed) -------
__device__ __nv_bfloat16 g_xhi[M_*D_],  g_xlo[M_*D_];
__device__ __nv_bfloat16 g_qhi[M_*D_],  g_qlo[M_*D_];
__device__ __nv_bfloat16 g_khi[M_*D_],  g_klo[M_*D_];
__device__ __nv_bfloat16 g_vhi[M_*D_],  g_vlo[M_*D_];
__device__ __nv_bfloat16 g_ahi[M_*D_],  g_alo[M_*D_];
__device__ __nv_bfloat16 g_wqhi[D_*D_], g_wqlo[D_*D_];
__device__ __nv_bfloat16 g_wkhi[D_*D_], g_wklo[D_*D_];
__device__ __nv_bfloat16 g_wvhi[D_*D_], g_wvlo[D_*D_];
__device__ __nv_bfloat16 g_wohi[D_*D_], g_wolo[D_*D_];

// ---------------- helpers ----------------------------------------------------
__device__ __forceinline__ uint32_t smem_u32(const void* p) {
    uint32_t a;
    asm("{ .reg .u64 t; cvta.to.shared.u64 t, %1; cvt.u32.u64 %0, t; }"
        : "=r"(a) : "l"(p));
    return a;
}
__device__ __forceinline__ void cp_async16(uint32_t saddr, const void* gaddr) {
    asm volatile("cp.async.cg.shared.global [%0], [%1], 16;"
                 :: "r"(saddr), "l"(gaddr) : "memory");
}
#define CP_COMMIT() asm volatile("cp.async.commit_group;" ::: "memory")
#define CP_WAIT(n)  asm volatile("cp.async.wait_group %0;" :: "n"(n) : "memory")

__device__ __forceinline__ void ldsm_x4(uint32_t* r, uint32_t addr) {
    asm volatile("ldmatrix.sync.aligned.m8n8.x4.shared.b16 {%0,%1,%2,%3}, [%4];"
                 : "=r"(r[0]), "=r"(r[1]), "=r"(r[2]), "=r"(r[3]) : "r"(addr));
}
__device__ __forceinline__ void ldsm_x4t(uint32_t* r, uint32_t addr) {
    asm volatile("ldmatrix.sync.aligned.m8n8.x4.trans.shared.b16 {%0,%1,%2,%3}, [%4];"
                 : "=r"(r[0]), "=r"(r[1]), "=r"(r[2]), "=r"(r[3]) : "r"(addr));
}
__device__ __forceinline__ void mma_bf16(float* c, const uint32_t* a, const uint32_t* b) {
    asm volatile(
        "mma.sync.aligned.m16n8k16.row.col.f32.bf16.bf16.f32 "
        "{%0,%1,%2,%3}, {%4,%5,%6,%7}, {%8,%9}, {%0,%1,%2,%3};"
        : "+f"(c[0]), "+f"(c[1]), "+f"(c[2]), "+f"(c[3])
        : "r"(a[0]), "r"(a[1]), "r"(a[2]), "r"(a[3]), "r"(b[0]), "r"(b[1]));
}
__device__ __forceinline__ void split2(float x0, float x1, uint32_t& hi, uint32_t& lo) {
    __nv_bfloat16 h0 = __float2bfloat16(x0);
    __nv_bfloat16 h1 = __float2bfloat16(x1);
    __nv_bfloat16 l0 = __float2bfloat16(x0 - __bfloat162float(h0));
    __nv_bfloat16 l1 = __float2bfloat16(x1 - __bfloat162float(h1));
    hi = (uint32_t)__bfloat16_as_ushort(h0) | ((uint32_t)__bfloat16_as_ushort(h1) << 16);
    lo = (uint32_t)__bfloat16_as_ushort(l0) | ((uint32_t)__bfloat16_as_ushort(l1) << 16);
}

// ---------------- split conversions ------------------------------------------
__global__ __launch_bounds__(256) void conv_split(
    const float* __restrict__ x, __nv_bfloat16* __restrict__ hi,
    __nv_bfloat16* __restrict__ lo, int n4)
{
    int i = blockIdx.x * blockDim.x + threadIdx.x;
    if (i >= n4) return;
    float4 v = ((const float4*)x)[i];
    uint32_t h0, l0, h1, l1;
    split2(v.x, v.y, h0, l0);
    split2(v.z, v.w, h1, l1);
    uint2 ho = { h0, h1 }, loo = { l0, l1 };
    ((uint2*)hi)[i] = ho;
    ((uint2*)lo)[i] = loo;
}

// all 4 weight matrices in one launch (blockIdx.y selects matrix)
__global__ __launch_bounds__(256) void conv_split_w(
    const float* w0, const float* w1, const float* w2, const float* w3,
    __nv_bfloat16* h0, __nv_bfloat16* l0, __nv_bfloat16* h1, __nv_bfloat16* l1,
    __nv_bfloat16* h2, __nv_bfloat16* l2, __nv_bfloat16* h3, __nv_bfloat16* l3)
{
    const float* x; __nv_bfloat16* hi; __nv_bfloat16* lo;
    if      (blockIdx.y == 0) { x = w0; hi = h0; lo = l0; }
    else if (blockIdx.y == 1) { x = w1; hi = h1; lo = l1; }
    else if (blockIdx.y == 2) { x = w2; hi = h2; lo = l2; }
    else                      { x = w3; hi = h3; lo = l3; }
    int i = blockIdx.x * blockDim.x + threadIdx.x;
    if (i >= D_*D_/4) return;
    float4 v = ((const float4*)x)[i];
    uint32_t a0, b0, a1, b1;
    split2(v.x, v.y, a0, b0);
    split2(v.z, v.w, a1, b1);
    uint2 ho = { a0, a1 }, loo = { b0, b1 };
    ((uint2*)hi)[i] = ho;
    ((uint2*)lo)[i] = loo;
}

// ---------------- mma.sync split-bf16 GEMM v2 ---------------------------------
// C[M][N] = A[M][K] @ W[N][K]^T + bias.  512 threads, 16 warps (4m x 4n),
// warp tile 32x32, BK=32 halves, 4-stage cp.async pipeline,
// XOR-swizzled 64B-row smem (chunk ^= (row>>1)&3) -> 32KB/stage.
#define BKH     32
#define MAT_B   (128*64)            // 8192 B per matrix per stage
#define STAGE_B (4*MAT_B)           // 32768
#define NSTAGE  4
#define GEMM_SMEM (NSTAGE*STAGE_B)  // 131072

template <bool SPLIT>
__global__ __launch_bounds__(512, 1) void gemm_mma_split(
    const __nv_bfloat16* __restrict__ Ahi, const __nv_bfloat16* __restrict__ Alo,
    const __nv_bfloat16* __restrict__ Whi, const __nv_bfloat16* __restrict__ Wlo,
    const float* __restrict__ bias, float* __restrict__ C,
    __nv_bfloat16* __restrict__ Chi, __nv_bfloat16* __restrict__ Clo)
{
    extern __shared__ __align__(1024) char smraw[];
    const uint32_t sb = smem_u32(smraw);

    const int tid = threadIdx.x;
    const int wid = tid >> 5;
    const int l   = tid & 31;
    const int wm  = wid & 3;        // m warp (4)
    const int wn  = wid >> 2;       // n warp (4)
    const int m0  = blockIdx.y * 128;
    const int n0  = blockIdx.x * 128;

    // copy mapping: row = tid>>2 (0..127), chunk c = tid&3 (16B each)
    const int crow = tid >> 2;
    const int cch  = tid & 3;
    const uint32_t sst = (uint32_t)(crow * 64 + ((cch ^ ((crow >> 1) & 3)) << 4));
    const __nv_bfloat16* gAh = Ahi + (size_t)(m0 + crow) * D_ + cch * 8;
    const __nv_bfloat16* gAl = Alo + (size_t)(m0 + crow) * D_ + cch * 8;
    const __nv_bfloat16* gWh = Whi + (size_t)(n0 + crow) * D_ + cch * 8;
    const __nv_bfloat16* gWl = Wlo + (size_t)(n0 + crow) * D_ + cch * 8;

    // ldmatrix addresses (swizzled, within one matrix); +1024B for mt/np=1
    const int rA  = wm * 32 + (l & 15);
    const int xkA = (rA >> 1) & 3;
    const int cA  = l >> 4;                       // 0..1
    const uint32_t aA_k0 = (uint32_t)(rA * 64 + ((cA       ^ xkA) << 4));
    const uint32_t aA_k1 = (uint32_t)(rA * 64 + (((cA + 2) ^ xkA) << 4));
    const int rB  = wn * 32 + (l & 7) + ((l >> 4) << 3);
    const int xkB = (rB >> 1) & 3;
    const int cB  = (l >> 3) & 1;
    const uint32_t aB_k0 = (uint32_t)(rB * 64 + ((cB       ^ xkB) << 4));
    const uint32_t aB_k1 = (uint32_t)(rB * 64 + (((cB + 2) ^ xkB) << 4));

    float acc[2][4][4];
#pragma unroll
    for (int mt = 0; mt < 2; mt++)
#pragma unroll
        for (int nt = 0; nt < 4; nt++)
#pragma unroll
            for (int e = 0; e < 4; e++) acc[mt][nt][e] = 0.f;

    const int NKT = D_ / BKH;   // 32

    auto issue_stage = [&](int s) {
        const uint32_t d = sb + (s & (NSTAGE-1)) * STAGE_B + sst;
        const int off = s * BKH;
        cp_async16(d + 0*MAT_B, gAh + off);
        cp_async16(d + 1*MAT_B, gAl + off);
        cp_async16(d + 2*MAT_B, gWh + off);
        cp_async16(d + 3*MAT_B, gWl + off);
    };

    issue_stage(0); CP_COMMIT();
    issue_stage(1); CP_COMMIT();
    issue_stage(2); CP_COMMIT();

    for (int kt = 0; kt < NKT; kt++) {
        if (kt + 3 < NKT) issue_stage(kt + 3);
        CP_COMMIT();
        CP_WAIT(3);
        __syncthreads();

        const uint32_t base = sb + (kt & (NSTAGE-1)) * STAGE_B;

#pragma unroll
        for (int kk = 0; kk < 2; kk++) {
            const uint32_t aA = base + (kk ? aA_k1 : aA_k0);
            const uint32_t aB = base + (kk ? aB_k1 : aB_k0);

            uint32_t ah[2][4];
            ldsm_x4(ah[0], aA + 0*MAT_B);
            ldsm_x4(ah[1], aA + 0*MAT_B + 1024);
            uint32_t wh[2][4];
            ldsm_x4(wh[0], aB + 2*MAT_B);
            ldsm_x4(wh[1], aB + 2*MAT_B + 1024);
#pragma unroll
            for (int mt = 0; mt < 2; mt++)
#pragma unroll
                for (int nt = 0; nt < 4; nt++)
                    mma_bf16(acc[mt][nt], ah[mt], &wh[nt >> 1][(nt & 1) * 2]);

            uint32_t wl[2][4];
            ldsm_x4(wl[0], aB + 3*MAT_B);
            ldsm_x4(wl[1], aB + 3*MAT_B + 1024);
#pragma unroll
            for (int mt = 0; mt < 2; mt++)
#pragma unroll
                for (int nt = 0; nt < 4; nt++)
                    mma_bf16(acc[mt][nt], ah[mt], &wl[nt >> 1][(nt & 1) * 2]);

            uint32_t al[2][4];
            ldsm_x4(al[0], aA + 1*MAT_B);
            ldsm_x4(al[1], aA + 1*MAT_B + 1024);
#pragma unroll
            for (int mt = 0; mt < 2; mt++)
#pragma unroll
                for (int nt = 0; nt < 4; nt++)
                    mma_bf16(acc[mt][nt], al[mt], &wh[nt >> 1][(nt & 1) * 2]);
        }

        __syncthreads();
    }

    const int rbase = m0 + wm*32 + (l >> 2);
    const int cbase = n0 + wn*32 + (l & 3) * 2;
#pragma unroll
    for (int mt = 0; mt < 2; mt++) {
#pragma unroll
        for (int nt = 0; nt < 4; nt++) {
            const int col = cbase + nt * 8;
            const float b0 = bias[col], b1 = bias[col + 1];
            const size_t r0o = (size_t)(rbase + mt*16) * D_ + col;
            const size_t r1o = (size_t)(rbase + mt*16 + 8) * D_ + col;
            if (SPLIT) {
                uint32_t hi, lo;
                split2(acc[mt][nt][0] + b0, acc[mt][nt][1] + b1, hi, lo);
                *(uint32_t*)(Chi + r0o) = hi;
                *(uint32_t*)(Clo + r0o) = lo;
                split2(acc[mt][nt][2] + b0, acc[mt][nt][3] + b1, hi, lo);
                *(uint32_t*)(Chi + r1o) = hi;
                *(uint32_t*)(Clo + r1o) = lo;
            } else {
                float2 v0 = { acc[mt][nt][0] + b0, acc[mt][nt][1] + b1 };
                float2 v1 = { acc[mt][nt][2] + b0, acc[mt][nt][3] + b1 };
                *(float2*)(C + r0o) = v0;
                *(float2*)(C + r1o) = v1;
            }
        }
    }
}

// ---------------- mma.sync split-bf16 flash attention ------------------------
// 128 queries/CTA, 8 warps x 16 q-rows. Software pipeline:
// prefetch K_{i+1} during PV_i, V_{i+1} during QK_{i+1} (single buffers).
#define AT_QP 72
#define AT_PP 136
#define oQh 0
#define oQl 18432
#define oKh 36864
#define oKl 55296
#define oVh 73728
#define oVl 92160
#define oPh 110592
#define oPl 145408
#define oMs 180224
#define ATT_SMEM (oMs + S_*4)    // 188416

__global__ __launch_bounds__(256, 1) void attn_mma(
    const __nv_bfloat16* __restrict__ Qh, const __nv_bfloat16* __restrict__ Ql,
    const __nv_bfloat16* __restrict__ Kh, const __nv_bfloat16* __restrict__ Kl,
    const __nv_bfloat16* __restrict__ Vh, const __nv_bfloat16* __restrict__ Vl,
    const int* __restrict__ mask,
    __nv_bfloat16* __restrict__ Ah, __nv_bfloat16* __restrict__ Al)
{
    extern __shared__ __align__(1024) char sm[];
    const uint32_t sb = smem_u32(sm);
    float* Mskf = (float*)(sm + oMs);

    const int tid = threadIdx.x;
    const int wid = tid >> 5;
    const int l   = tid & 31;
    const int b   = blockIdx.y >> 4;
    const int h   = blockIdx.y & 15;
    const int q0  = blockIdx.x * 128;

    const int crow = tid >> 1, chc = (tid & 1) * 32;
    const uint32_t cds = (uint32_t)(crow * AT_QP + chc) * 2;
    const size_t gKVrow = (size_t)(b*S_ + crow) * D_ + h*DH_ + chc;

    auto issue_K = [&](int kt) {
        const size_t g = gKVrow + (size_t)kt * 128 * D_;
#pragma unroll
        for (int j = 0; j < 4; j++) {
            cp_async16(sb + oKh + cds + j*16, Kh + g + j*8);
            cp_async16(sb + oKl + cds + j*16, Kl + g + j*8);
        }
    };
    auto issue_V = [&](int kt) {
        const size_t g = gKVrow + (size_t)kt * 128 * D_;
#pragma unroll
        for (int j = 0; j < 4; j++) {
            cp_async16(sb + oVh + cds + j*16, Vh + g + j*8);
            cp_async16(sb + oVl + cds + j*16, Vl + g + j*8);
        }
    };

    // mask -> smem
    for (int i = tid; i < S_; i += 256)
        Mskf[i] = (float)mask[(size_t)b*S_ + i];

    // prologue: Q + K0 (group), V0 (group)
    {
        const size_t g = (size_t)(b*S_ + q0 + crow) * D_ + h*DH_ + chc;
#pragma unroll
        for (int j = 0; j < 4; j++) {
            cp_async16(sb + oQh + cds + j*16, Qh + g + j*8);
            cp_async16(sb + oQl + cds + j*16, Ql + g + j*8);
        }
    }
    issue_K(0);
    CP_COMMIT();
    issue_V(0);
    CP_COMMIT();

    float m_run[2] = { -1e30f, -1e30f };
    float l_run[2] = { 0.f, 0.f };
    float o[8][4];
#pragma unroll
    for (int nt = 0; nt < 8; nt++)
#pragma unroll
        for (int e = 0; e < 4; e++) o[nt][e] = 0.f;

    const uint32_t aQh = sb + oQh + (uint32_t)(((wid<<4) + (l & 15)) * AT_QP + ((l >> 4) << 3)) * 2;
    const uint32_t aQl = aQh + (oQl - oQh);
    const uint32_t aKo = (uint32_t)(((l & 7) + ((l >> 4) << 3)) * AT_QP + (((l >> 3) & 1) << 3)) * 2;
    const uint32_t aPh = sb + oPh + (uint32_t)(((wid<<4) + (l & 15)) * AT_PP + ((l >> 4) << 3)) * 2;
    const uint32_t aPl = aPh + (oPl - oPh);
    const uint32_t aVo = (uint32_t)(((l & 7) + (((l >> 3) & 1) << 3)) * AT_QP + ((l >> 4) << 3)) * 2;

    const int r0 = l >> 2;
    const int c0 = (l & 3) * 2;

    for (int kt = 0; kt < S_/128; kt++) {
        CP_WAIT(1);            // K_kt (+Q, first iter) ready; V_kt may be pending
        __syncthreads();

        // ---- QK^T: s[16][4] ----
        float s[16][4];
#pragma unroll
        for (int nt = 0; nt < 16; nt++)
#pragma unroll
            for (int e = 0; e < 4; e++) s[nt][e] = 0.f;

#pragma unroll
        for (int ks = 0; ks < 4; ks++) {
            uint32_t qh[4], ql[4];
            ldsm_x4(qh, aQh + ks*32);
            ldsm_x4(ql, aQl + ks*32);
#pragma unroll
            for (int np = 0; np < 8; np++) {
                const uint32_t ka = sb + aKo + np*(16*AT_QP*2) + ks*32;
                uint32_t kh[4], kl[4];
                ldsm_x4(kh, ka + oKh);
                ldsm_x4(kl, ka + oKl);
                mma_bf16(s[2*np],   qh, kh);     mma_bf16(s[2*np+1], qh, kh+2);
                mma_bf16(s[2*np],   qh, kl);     mma_bf16(s[2*np+1], qh, kl+2);
                mma_bf16(s[2*np],   ql, kh);     mma_bf16(s[2*np+1], ql, kh+2);
            }
        }

        // ---- mask + scale + online softmax ----
        const int kb = kt * 128;
        float mx0 = -1e30f, mx1 = -1e30f;
#pragma unroll
        for (int nt = 0; nt < 16; nt++) {
            const float k0 = Mskf[kb + nt*8 + c0];
            const float k1 = Mskf[kb + nt*8 + c0 + 1];
            s[nt][0] = (k0 != 0.f) ? s[nt][0] * 0.125f : -1e30f;
            s[nt][1] = (k1 != 0.f) ? s[nt][1] * 0.125f : -1e30f;
            s[nt][2] = (k0 != 0.f) ? s[nt][2] * 0.125f : -1e30f;
            s[nt][3] = (k1 != 0.f) ? s[nt][3] * 0.125f : -1e30f;
            mx0 = fmaxf(mx0, fmaxf(s[nt][0], s[nt][1]));
            mx1 = fmaxf(mx1, fmaxf(s[nt][2], s[nt][3]));
        }
        mx0 = fmaxf(mx0, __shfl_xor_sync(0xffffffffu, mx0, 1));
        mx0 = fmaxf(mx0, __shfl_xor_sync(0xffffffffu, mx0, 2));
        mx1 = fmaxf(mx1, __shfl_xor_sync(0xffffffffu, mx1, 1));
        mx1 = fmaxf(mx1, __shfl_xor_sync(0xffffffffu, mx1, 2));

        const float mn0 = fmaxf(m_run[0], mx0);
        const float mn1 = fmaxf(m_run[1], mx1);
        const float al0 = __expf(m_run[0] - mn0);
        const float al1 = __expf(m_run[1] - mn1);
        m_run[0] = mn0; m_run[1] = mn1;

        float su0 = 0.f, su1 = 0.f;
#pragma unroll
        for (int nt = 0; nt < 16; nt++) {
            s[nt][0] = __expf(s[nt][0] - mn0);
            s[nt][1] = __expf(s[nt][1] - mn0);
            s[nt][2] = __expf(s[nt][2] - mn1);
            s[nt][3] = __expf(s[nt][3] - mn1);
            su0 += s[nt][0] + s[nt][1];
            su1 += s[nt][2] + s[nt][3];
        }
        su0 += __shfl_xor_sync(0xffffffffu, su0, 1);
        su0 += __shfl_xor_sync(0xffffffffu, su0, 2);
        su1 += __shfl_xor_sync(0xffffffffu, su1, 1);
        su1 += __shfl_xor_sync(0xffffffffu, su1, 2);
        l_run[0] = l_run[0] * al0 + su0;
        l_run[1] = l_run[1] * al1 + su1;

#pragma unroll
        for (int nt = 0; nt < 8; nt++) {
            o[nt][0] *= al0; o[nt][1] *= al0;
            o[nt][2] *= al1; o[nt][3] *= al1;
        }

        // ---- store P hi/lo ----
        {
            char* p0 = sm + oPh + (size_t)(((wid<<4) + r0) * AT_PP + c0) * 2;
            char* p1 = p0 + 8 * AT_PP * 2;
            const ptrdiff_t dlo = oPl - oPh;
#pragma unroll
            for (int nt = 0; nt < 16; nt++) {
                uint32_t hi, lo;
                split2(s[nt][0], s[nt][1], hi, lo);
                *(uint32_t*)(p0 + nt*16)       = hi;
                *(uint32_t*)(p0 + nt*16 + dlo) = lo;
                split2(s[nt][2], s[nt][3], hi, lo);
                *(uint32_t*)(p1 + nt*16)       = hi;
                *(uint32_t*)(p1 + nt*16 + dlo) = lo;
            }
        }

        CP_WAIT(0);            // V_kt arrived (all earlier groups done)
        __syncthreads();       // P visible; all warps done with K_kt, V ready

        if (kt + 1 < S_/128) issue_K(kt + 1);   // overlaps PV below
        CP_COMMIT();

        // ---- PV ----
#pragma unroll
        for (int ks = 0; ks < 8; ks++) {
            uint32_t ph[4], pl[4];
            ldsm_x4(ph, aPh + ks*32);
            ldsm_x4(pl, aPl + ks*32);
#pragma unroll
            for (int vb = 0; vb < 4; vb++) {
                const uint32_t va = sb + aVo + ks*(16*AT_QP*2) + vb*32;
                uint32_t vh[4], vl[4];
                ldsm_x4t(vh, va + oVh);
                ldsm_x4t(vl, va + oVl);
                mma_bf16(o[2*vb],   ph, vh);     mma_bf16(o[2*vb+1], ph, vh+2);
                mma_bf16(o[2*vb],   ph, vl);     mma_bf16(o[2*vb+1], ph, vl+2);
                mma_bf16(o[2*vb],   pl, vh);     mma_bf16(o[2*vb+1], pl, vh+2);
            }
        }

        __syncthreads();       // all warps done with V_kt (and P)
        if (kt + 1 < S_/128) issue_V(kt + 1);   // overlaps next QK
        CP_COMMIT();
    }

    // ---- epilogue ----
    const float i0 = 1.f / l_run[0];
    const float i1 = 1.f / l_run[1];
    const size_t row0 = (size_t)(b*S_ + q0 + (wid<<4) + r0);
    const size_t row1 = row0 + 8;
#pragma unroll
    for (int nt = 0; nt < 8; nt++) {
        const int col = h*DH_ + nt*8 + c0;
        uint32_t hi, lo;
        split2(o[nt][0]*i0, o[nt][1]*i0, hi, lo);
        *(uint32_t*)(Ah + row0*D_ + col) = hi;
        *(uint32_t*)(Al + row0*D_ + col) = lo;
        split2(o[nt][2]*i1, o[nt][3]*i1, hi, lo);
        *(uint32_t*)(Ah + row1*D_ + col) = hi;
        *(uint32_t*)(Al + row1*D_ + col) = lo;
    }
}

// ---------------------------------------------------------------------------
extern "C" void kernel_launch(void* const* d_in, const int* in_sizes, int n_in,
                              void* d_out, int out_size)
{
    const float* x    = (const float*)d_in[0];
    const int*   mask = (const int*)  d_in[1];
    const float* Wq   = (const float*)d_in[2];
    const float* bq   = (const float*)d_in[3];
    const float* Wk   = (const float*)d_in[4];
    const float* bk   = (const float*)d_in[5];
    const float* Wv   = (const float*)d_in[6];
    const float* bv   = (const float*)d_in[7];
    const float* Wo   = (const float*)d_in[8];
    const float* bo   = (const float*)d_in[9];
    float* out = (float*)d_out;

    __nv_bfloat16 *xhi, *xlo, *qhi, *qlo, *khi, *klo, *vhi, *vlo, *ahi, *alo;
    __nv_bfloat16 *wqh, *wql, *wkh, *wkl, *wvh, *wvl, *woh, *wol;
    cudaGetSymbolAddress((void**)&xhi, g_xhi);
    cudaGetSymbolAddress((void**)&xlo, g_xlo);
    cudaGetSymbolAddress((void**)&qhi, g_qhi);
    cudaGetSymbolAddress((void**)&qlo, g_qlo);
    cudaGetSymbolAddress((void**)&khi, g_khi);
    cudaGetSymbolAddress((void**)&klo, g_klo);
    cudaGetSymbolAddress((void**)&vhi, g_vhi);
    cudaGetSymbolAddress((void**)&vlo, g_vlo);
    cudaGetSymbolAddress((void**)&ahi, g_ahi);
    cudaGetSymbolAddress((void**)&alo, g_alo);
    cudaGetSymbolAddress((void**)&wqh, g_wqhi);
    cudaGetSymbolAddress((void**)&wql, g_wqlo);
    cudaGetSymbolAddress((void**)&wkh, g_wkhi);
    cudaGetSymbolAddress((void**)&wkl, g_wklo);
    cudaGetSymbolAddress((void**)&wvh, g_wvhi);
    cudaGetSymbolAddress((void**)&wvl, g_wvlo);
    cudaGetSymbolAddress((void**)&woh, g_wohi);
    cudaGetSymbolAddress((void**)&wol, g_wolo);

    cudaFuncSetAttribute(gemm_mma_split<true>,
                         cudaFuncAttributeMaxDynamicSharedMemorySize, GEMM_SMEM);
    cudaFuncSetAttribute(gemm_mma_split<false>,
                         cudaFuncAttributeMaxDynamicSharedMemorySize, GEMM_SMEM);
    cudaFuncSetAttribute(attn_mma,
                         cudaFuncAttributeMaxDynamicSharedMemorySize, ATT_SMEM);

    conv_split<<<(M_*D_/4)/256, 256>>>(x, xhi, xlo, M_*D_/4);
    dim3 gw((D_*D_/4)/256, 4);
    conv_split_w<<<gw, 256>>>(Wq, Wk, Wv, Wo,
                              wqh, wql, wkh, wkl, wvh, wvl, woh, wol);

    dim3 gg(D_/128, M_/128);   // (8, 32)
    gemm_mma_split<true><<<gg, 512, GEMM_SMEM>>>(xhi, xlo, wqh, wql, bq, nullptr, qhi, qlo);
    gemm_mma_split<true><<<gg, 512, GEMM_SMEM>>>(xhi, xlo, wkh, wkl, bk, nullptr, khi, klo);
    gemm_mma_split<true><<<gg, 512, GEMM_SMEM>>>(xhi, xlo, wvh, wvl, bv, nullptr, vhi, vlo);

    dim3 ga(S_/128, B_*H_);    // (16, 32)
    attn_mma<<<ga, 256, ATT_SMEM>>>(qhi, qlo, khi, klo, vhi, vlo, mask, ahi, alo);

    gemm_mma_split<false><<<gg, 512, GEMM_SMEM>>>(ahi, alo, woh, wol, bo, out, nullptr, nullptr);
}

// round 9
// speedup vs baseline: 6.2193x; 1.5021x over previous
#include <cuda_runtime.h>
#include <cuda_fp16.h>
#include <cstdint>
#include <math.h>

#define B_  2
#define S_  2048
#define H_  16
#define DH_ 64
#define D_  1024
#define M_  (B_*S_)   // 4096

// ---------------- scratch (__device__ globals; no allocation allowed) -------
__device__ __half g_xhi[M_*D_],  g_xlo[M_*D_];
__device__ __half g_qh[M_*D_];
__device__ __half g_kh[M_*D_];
__device__ __half g_vh[M_*D_];
__device__ __half g_ahi[M_*D_],  g_alo[M_*D_];
__device__ __half g_wqhi[D_*D_], g_wqlo[D_*D_];
__device__ __half g_wkhi[D_*D_], g_wklo[D_*D_];
__device__ __half g_wvhi[D_*D_], g_wvlo[D_*D_];
__device__ __half g_wohi[D_*D_], g_wolo[D_*D_];

// ---------------- helpers ----------------------------------------------------
__device__ __forceinline__ uint32_t smem_u32(const void* p) {
    uint32_t a;
    asm("{ .reg .u64 t; cvta.to.shared.u64 t, %1; cvt.u32.u64 %0, t; }"
        : "=r"(a) : "l"(p));
    return a;
}
__device__ __forceinline__ void cp_async16(uint32_t saddr, const void* gaddr) {
    asm volatile("cp.async.cg.shared.global [%0], [%1], 16;"
                 :: "r"(saddr), "l"(gaddr) : "memory");
}
#define CP_COMMIT() asm volatile("cp.async.commit_group;" ::: "memory")
#define CP_WAIT(n)  asm volatile("cp.async.wait_group %0;" :: "n"(n) : "memory")

__device__ __forceinline__ void ldsm_x4(uint32_t* r, uint32_t addr) {
    asm volatile("ldmatrix.sync.aligned.m8n8.x4.shared.b16 {%0,%1,%2,%3}, [%4];"
                 : "=r"(r[0]), "=r"(r[1]), "=r"(r[2]), "=r"(r[3]) : "r"(addr));
}
__device__ __forceinline__ void ldsm_x4t(uint32_t* r, uint32_t addr) {
    asm volatile("ldmatrix.sync.aligned.m8n8.x4.trans.shared.b16 {%0,%1,%2,%3}, [%4];"
                 : "=r"(r[0]), "=r"(r[1]), "=r"(r[2]), "=r"(r[3]) : "r"(addr));
}
__device__ __forceinline__ void mma_f16(float* c, const uint32_t* a, const uint32_t* b) {
    asm volatile(
        "mma.sync.aligned.m16n8k16.row.col.f32.f16.f16.f32 "
        "{%0,%1,%2,%3}, {%4,%5,%6,%7}, {%8,%9}, {%0,%1,%2,%3};"
        : "+f"(c[0]), "+f"(c[1]), "+f"(c[2]), "+f"(c[3])
        : "r"(a[0]), "r"(a[1]), "r"(a[2]), "r"(a[3]), "r"(b[0]), "r"(b[1]));
}
// split two floats into fp16 hi pair + fp16 lo pair
__device__ __forceinline__ void split2h(float x0, float x1, uint32_t& hi, uint32_t& lo) {
    __half h0 = __float2half_rn(x0);
    __half h1 = __float2half_rn(x1);
    __half l0 = __float2half_rn(x0 - __half2float(h0));
    __half l1 = __float2half_rn(x1 - __half2float(h1));
    hi = (uint32_t)__half_as_ushort(h0) | ((uint32_t)__half_as_ushort(h1) << 16);
    lo = (uint32_t)__half_as_ushort(l0) | ((uint32_t)__half_as_ushort(l1) << 16);
}
__device__ __forceinline__ uint32_t pack2h(float x0, float x1) {
    __half h0 = __float2half_rn(x0);
    __half h1 = __float2half_rn(x1);
    return (uint32_t)__half_as_ushort(h0) | ((uint32_t)__half_as_ushort(h1) << 16);
}

// ---------------- split conversions ------------------------------------------
__global__ __launch_bounds__(256) void conv_split(
    const float* __restrict__ x, __half* __restrict__ hi,
    __half* __restrict__ lo, int n4)
{
    int i = blockIdx.x * blockDim.x + threadIdx.x;
    if (i >= n4) return;
    float4 v = ((const float4*)x)[i];
    uint32_t h0, l0, h1, l1;
    split2h(v.x, v.y, h0, l0);
    split2h(v.z, v.w, h1, l1);
    uint2 ho = { h0, h1 }, loo = { l0, l1 };
    ((uint2*)hi)[i] = ho;
    ((uint2*)lo)[i] = loo;
}

__global__ __launch_bounds__(256) void conv_split_w(
    const float* w0, const float* w1, const float* w2, const float* w3,
    __half* h0, __half* l0, __half* h1, __half* l1,
    __half* h2, __half* l2, __half* h3, __half* l3)
{
    const float* x; __half* hi; __half* lo;
    if      (blockIdx.y == 0) { x = w0; hi = h0; lo = l0; }
    else if (blockIdx.y == 1) { x = w1; hi = h1; lo = l1; }
    else if (blockIdx.y == 2) { x = w2; hi = h2; lo = l2; }
    else                      { x = w3; hi = h3; lo = l3; }
    int i = blockIdx.x * blockDim.x + threadIdx.x;
    if (i >= D_*D_/4) return;
    float4 v = ((const float4*)x)[i];
    uint32_t a0, b0, a1, b1;
    split2h(v.x, v.y, a0, b0);
    split2h(v.z, v.w, a1, b1);
    uint2 ho = { a0, a1 }, loo = { b0, b1 };
    ((uint2*)hi)[i] = ho;
    ((uint2*)lo)[i] = loo;
}

// ---------------- mma.sync split-fp16 GEMM ------------------------------------
// C[M][N] = A[M][K] @ W[N][K]^T + bias.  512 threads, 16 warps (4m x 4n),
// warp tile 32x32, BK=32 halves, 4-stage cp.async pipeline, XOR-swizzled smem.
// 3-pass: Ahi*Whi + Ahi*Wlo + Alo*Whi (fp32 accum).
// MODE 0: f32 output.  MODE 1: fp16 single output (for attention inputs).
#define BKH     32
#define MAT_B   (128*64)
#define STAGE_B (4*MAT_B)
#define NSTAGE  4
#define GEMM_SMEM (NSTAGE*STAGE_B)  // 131072

template <int MODE>
__global__ __launch_bounds__(512, 1) void gemm_mma_split(
    const __half* __restrict__ Ahi, const __half* __restrict__ Alo,
    const __half* __restrict__ Whi, const __half* __restrict__ Wlo,
    const float* __restrict__ bias, float* __restrict__ C,
    __half* __restrict__ Ch)
{
    extern __shared__ __align__(1024) char smraw[];
    const uint32_t sb = smem_u32(smraw);

    const int tid = threadIdx.x;
    const int wid = tid >> 5;
    const int l   = tid & 31;
    const int wm  = wid & 3;
    const int wn  = wid >> 2;
    const int m0  = blockIdx.y * 128;
    const int n0  = blockIdx.x * 128;

    const int crow = tid >> 2;
    const int cch  = tid & 3;
    const uint32_t sst = (uint32_t)(crow * 64 + ((cch ^ ((crow >> 1) & 3)) << 4));
    const __half* gAh = Ahi + (size_t)(m0 + crow) * D_ + cch * 8;
    const __half* gAl = Alo + (size_t)(m0 + crow) * D_ + cch * 8;
    const __half* gWh = Whi + (size_t)(n0 + crow) * D_ + cch * 8;
    const __half* gWl = Wlo + (size_t)(n0 + crow) * D_ + cch * 8;

    const int rA  = wm * 32 + (l & 15);
    const int xkA = (rA >> 1) & 3;
    const int cA  = l >> 4;
    const uint32_t aA_k0 = (uint32_t)(rA * 64 + ((cA       ^ xkA) << 4));
    const uint32_t aA_k1 = (uint32_t)(rA * 64 + (((cA + 2) ^ xkA) << 4));
    const int rB  = wn * 32 + (l & 7) + ((l >> 4) << 3);
    const int xkB = (rB >> 1) & 3;
    const int cB  = (l >> 3) & 1;
    const uint32_t aB_k0 = (uint32_t)(rB * 64 + ((cB       ^ xkB) << 4));
    const uint32_t aB_k1 = (uint32_t)(rB * 64 + (((cB + 2) ^ xkB) << 4));

    float acc[2][4][4];
#pragma unroll
    for (int mt = 0; mt < 2; mt++)
#pragma unroll
        for (int nt = 0; nt < 4; nt++)
#pragma unroll
            for (int e = 0; e < 4; e++) acc[mt][nt][e] = 0.f;

    const int NKT = D_ / BKH;   // 32

    auto issue_stage = [&](int s) {
        const uint32_t d = sb + (s & (NSTAGE-1)) * STAGE_B + sst;
        const int off = s * BKH;
        cp_async16(d + 0*MAT_B, gAh + off);
        cp_async16(d + 1*MAT_B, gAl + off);
        cp_async16(d + 2*MAT_B, gWh + off);
        cp_async16(d + 3*MAT_B, gWl + off);
    };

    issue_stage(0); CP_COMMIT();
    issue_stage(1); CP_COMMIT();
    issue_stage(2); CP_COMMIT();

    for (int kt = 0; kt < NKT; kt++) {
        if (kt + 3 < NKT) issue_stage(kt + 3);
        CP_COMMIT();
        CP_WAIT(3);
        __syncthreads();

        const uint32_t base = sb + (kt & (NSTAGE-1)) * STAGE_B;

#pragma unroll
        for (int kk = 0; kk < 2; kk++) {
            const uint32_t aA = base + (kk ? aA_k1 : aA_k0);
            const uint32_t aB = base + (kk ? aB_k1 : aB_k0);

            uint32_t ah[2][4];
            ldsm_x4(ah[0], aA + 0*MAT_B);
            ldsm_x4(ah[1], aA + 0*MAT_B + 1024);
            uint32_t wh[2][4];
            ldsm_x4(wh[0], aB + 2*MAT_B);
            ldsm_x4(wh[1], aB + 2*MAT_B + 1024);
#pragma unroll
            for (int mt = 0; mt < 2; mt++)
#pragma unroll
                for (int nt = 0; nt < 4; nt++)
                    mma_f16(acc[mt][nt], ah[mt], &wh[nt >> 1][(nt & 1) * 2]);

            uint32_t wl[2][4];
            ldsm_x4(wl[0], aB + 3*MAT_B);
            ldsm_x4(wl[1], aB + 3*MAT_B + 1024);
#pragma unroll
            for (int mt = 0; mt < 2; mt++)
#pragma unroll
                for (int nt = 0; nt < 4; nt++)
                    mma_f16(acc[mt][nt], ah[mt], &wl[nt >> 1][(nt & 1) * 2]);

            uint32_t al[2][4];
            ldsm_x4(al[0], aA + 1*MAT_B);
            ldsm_x4(al[1], aA + 1*MAT_B + 1024);
#pragma unroll
            for (int mt = 0; mt < 2; mt++)
#pragma unroll
                for (int nt = 0; nt < 4; nt++)
                    mma_f16(acc[mt][nt], al[mt], &wh[nt >> 1][(nt & 1) * 2]);
        }

        __syncthreads();
    }

    const int rbase = m0 + wm*32 + (l >> 2);
    const int cbase = n0 + wn*32 + (l & 3) * 2;
#pragma unroll
    for (int mt = 0; mt < 2; mt++) {
#pragma unroll
        for (int nt = 0; nt < 4; nt++) {
            const int col = cbase + nt * 8;
            const float b0 = bias[col], b1 = bias[col + 1];
            const size_t r0o = (size_t)(rbase + mt*16) * D_ + col;
            const size_t r1o = (size_t)(rbase + mt*16 + 8) * D_ + col;
            if (MODE == 1) {
                *(uint32_t*)(Ch + r0o) = pack2h(acc[mt][nt][0] + b0, acc[mt][nt][1] + b1);
                *(uint32_t*)(Ch + r1o) = pack2h(acc[mt][nt][2] + b0, acc[mt][nt][3] + b1);
            } else {
                float2 v0 = { acc[mt][nt][0] + b0, acc[mt][nt][1] + b1 };
                float2 v1 = { acc[mt][nt][2] + b0, acc[mt][nt][3] + b1 };
                *(float2*)(C + r0o) = v0;
                *(float2*)(C + r1o) = v1;
            }
        }
    }
}

// ---------------- fp16 single-pass flash attention ----------------------------
// 128 queries/CTA, 8 warps x 16 q-rows. Q,K,V,P all plain fp16 (single mma pass
// per product). Output split to fp16 hi/lo for the 3-pass output projection.
#define AT_QP 72
#define AT_PP 136
#define oQ 0
#define oK 18432
#define oV 36864
#define oP 55296
#define oM 90112
#define ATT_SMEM (oM + S_*4)   // 98304

__global__ __launch_bounds__(256, 2) void attn_mma(
    const __half* __restrict__ Qh, const __half* __restrict__ Kh,
    const __half* __restrict__ Vh, const int* __restrict__ mask,
    __half* __restrict__ Ah, __half* __restrict__ Al)
{
    extern __shared__ __align__(1024) char sm[];
    const uint32_t sb = smem_u32(sm);
    float* Mskf = (float*)(sm + oM);

    const int tid = threadIdx.x;
    const int wid = tid >> 5;
    const int l   = tid & 31;
    const int b   = blockIdx.y >> 4;
    const int h   = blockIdx.y & 15;
    const int q0  = blockIdx.x * 128;

    const int crow = tid >> 1, chc = (tid & 1) * 32;
    const uint32_t cds = (uint32_t)(crow * AT_QP + chc) * 2;
    const size_t gKVrow = (size_t)(b*S_ + crow) * D_ + h*DH_ + chc;

    auto issue_K = [&](int kt) {
        const size_t g = gKVrow + (size_t)kt * 128 * D_;
#pragma unroll
        for (int j = 0; j < 4; j++)
            cp_async16(sb + oK + cds + j*16, Kh + g + j*8);
    };
    auto issue_V = [&](int kt) {
        const size_t g = gKVrow + (size_t)kt * 128 * D_;
#pragma unroll
        for (int j = 0; j < 4; j++)
            cp_async16(sb + oV + cds + j*16, Vh + g + j*8);
    };

    for (int i = tid; i < S_; i += 256)
        Mskf[i] = (float)mask[(size_t)b*S_ + i];

    {
        const size_t g = (size_t)(b*S_ + q0 + crow) * D_ + h*DH_ + chc;
#pragma unroll
        for (int j = 0; j < 4; j++)
            cp_async16(sb + oQ + cds + j*16, Qh + g + j*8);
    }
    issue_K(0);
    CP_COMMIT();
    issue_V(0);
    CP_COMMIT();

    float m_run[2] = { -1e30f, -1e30f };
    float l_run[2] = { 0.f, 0.f };
    float o[8][4];
#pragma unroll
    for (int nt = 0; nt < 8; nt++)
#pragma unroll
        for (int e = 0; e < 4; e++) o[nt][e] = 0.f;

    const uint32_t aQ  = sb + oQ + (uint32_t)(((wid<<4) + (l & 15)) * AT_QP + ((l >> 4) << 3)) * 2;
    const uint32_t aKo = (uint32_t)(((l & 7) + ((l >> 4) << 3)) * AT_QP + (((l >> 3) & 1) << 3)) * 2;
    const uint32_t aP  = sb + oP + (uint32_t)(((wid<<4) + (l & 15)) * AT_PP + ((l >> 4) << 3)) * 2;
    const uint32_t aVo = (uint32_t)(((l & 7) + (((l >> 3) & 1) << 3)) * AT_QP + ((l >> 4) << 3)) * 2;

    const int r0 = l >> 2;
    const int c0 = (l & 3) * 2;

    for (int kt = 0; kt < S_/128; kt++) {
        CP_WAIT(1);            // K_kt (+Q first iter) ready
        __syncthreads();

        // ---- QK^T (single pass): s[16][4] ----
        float s[16][4];
#pragma unroll
        for (int nt = 0; nt < 16; nt++)
#pragma unroll
            for (int e = 0; e < 4; e++) s[nt][e] = 0.f;

#pragma unroll
        for (int ks = 0; ks < 4; ks++) {
            uint32_t q[4];
            ldsm_x4(q, aQ + ks*32);
#pragma unroll
            for (int np = 0; np < 8; np++) {
                uint32_t k[4];
                ldsm_x4(k, sb + oK + aKo + np*(16*AT_QP*2) + ks*32);
                mma_f16(s[2*np],   q, k);
                mma_f16(s[2*np+1], q, k+2);
            }
        }

        // ---- mask + scale + online softmax ----
        const int kb = kt * 128;
        float mx0 = -1e30f, mx1 = -1e30f;
#pragma unroll
        for (int nt = 0; nt < 16; nt++) {
            const float k0 = Mskf[kb + nt*8 + c0];
            const float k1 = Mskf[kb + nt*8 + c0 + 1];
            s[nt][0] = (k0 != 0.f) ? s[nt][0] * 0.125f : -1e30f;
            s[nt][1] = (k1 != 0.f) ? s[nt][1] * 0.125f : -1e30f;
            s[nt][2] = (k0 != 0.f) ? s[nt][2] * 0.125f : -1e30f;
            s[nt][3] = (k1 != 0.f) ? s[nt][3] * 0.125f : -1e30f;
            mx0 = fmaxf(mx0, fmaxf(s[nt][0], s[nt][1]));
            mx1 = fmaxf(mx1, fmaxf(s[nt][2], s[nt][3]));
        }
        mx0 = fmaxf(mx0, __shfl_xor_sync(0xffffffffu, mx0, 1));
        mx0 = fmaxf(mx0, __shfl_xor_sync(0xffffffffu, mx0, 2));
        mx1 = fmaxf(mx1, __shfl_xor_sync(0xffffffffu, mx1, 1));
        mx1 = fmaxf(mx1, __shfl_xor_sync(0xffffffffu, mx1, 2));

        const float mn0 = fmaxf(m_run[0], mx0);
        const float mn1 = fmaxf(m_run[1], mx1);
        const float al0 = __expf(m_run[0] - mn0);
        const float al1 = __expf(m_run[1] - mn1);
        m_run[0] = mn0; m_run[1] = mn1;

        float su0 = 0.f, su1 = 0.f;
#pragma unroll
        for (int nt = 0; nt < 16; nt++) {
            s[nt][0] = __expf(s[nt][0] - mn0);
            s[nt][1] = __expf(s[nt][1] - mn0);
            s[nt][2] = __expf(s[nt][2] - mn1);
            s[nt][3] = __expf(s[nt][3] - mn1);
            su0 += s[nt][0] + s[nt][1];
            su1 += s[nt][2] + s[nt][3];
        }
        su0 += __shfl_xor_sync(0xffffffffu, su0, 1);
        su0 += __shfl_xor_sync(0xffffffffu, su0, 2);
        su1 += __shfl_xor_sync(0xffffffffu, su1, 1);
        su1 += __shfl_xor_sync(0xffffffffu, su1, 2);
        l_run[0] = l_run[0] * al0 + su0;
        l_run[1] = l_run[1] * al1 + su1;

#pragma unroll
        for (int nt = 0; nt < 8; nt++) {
            o[nt][0] *= al0; o[nt][1] *= al0;
            o[nt][2] *= al1; o[nt][3] *= al1;
        }

        // ---- store P (fp16 single) ----
        {
            char* p0 = sm + oP + (size_t)(((wid<<4) + r0) * AT_PP + c0) * 2;
            char* p1 = p0 + 8 * AT_PP * 2;
#pragma unroll
            for (int nt = 0; nt < 16; nt++) {
                *(uint32_t*)(p0 + nt*16) = pack2h(s[nt][0], s[nt][1]);
                *(uint32_t*)(p1 + nt*16) = pack2h(s[nt][2], s[nt][3]);
            }
        }

        CP_WAIT(0);            // V_kt arrived
        __syncthreads();       // P visible; K_kt reads done

        if (kt + 1 < S_/128) issue_K(kt + 1);   // overlaps PV
        CP_COMMIT();

        // ---- PV (single pass) ----
#pragma unroll
        for (int ks = 0; ks < 8; ks++) {
            uint32_t p[4];
            ldsm_x4(p, aP + ks*32);
#pragma unroll
            for (int vb = 0; vb < 4; vb++) {
                uint32_t v[4];
                ldsm_x4t(v, sb + oV + aVo + ks*(16*AT_QP*2) + vb*32);
                mma_f16(o[2*vb],   p, v);
                mma_f16(o[2*vb+1], p, v+2);
            }
        }

        __syncthreads();       // V_kt reads done
        if (kt + 1 < S_/128) issue_V(kt + 1);   // overlaps next QK
        CP_COMMIT();
    }

    // ---- epilogue: normalize, split to fp16 hi/lo ----
    const float i0 = 1.f / l_run[0];
    const float i1 = 1.f / l_run[1];
    const size_t row0 = (size_t)(b*S_ + q0 + (wid<<4) + r0);
    const size_t row1 = row0 + 8;
#pragma unroll
    for (int nt = 0; nt < 8; nt++) {
        const int col = h*DH_ + nt*8 + c0;
        uint32_t hi, lo;
        split2h(o[nt][0]*i0, o[nt][1]*i0, hi, lo);
        *(uint32_t*)(Ah + row0*D_ + col) = hi;
        *(uint32_t*)(Al + row0*D_ + col) = lo;
        split2h(o[nt][2]*i1, o[nt][3]*i1, hi, lo);
        *(uint32_t*)(Ah + row1*D_ + col) = hi;
        *(uint32_t*)(Al + row1*D_ + col) = lo;
    }
}

// ---------------------------------------------------------------------------
extern "C" void kernel_launch(void* const* d_in, const int* in_sizes, int n_in,
                              void* d_out, int out_size)
{
    const float* x    = (const float*)d_in[0];
    const int*   mask = (const int*)  d_in[1];
    const float* Wq   = (const float*)d_in[2];
    const float* bq   = (const float*)d_in[3];
    const float* Wk   = (const float*)d_in[4];
    const float* bk   = (const float*)d_in[5];
    const float* Wv   = (const float*)d_in[6];
    const float* bv   = (const float*)d_in[7];
    const float* Wo   = (const float*)d_in[8];
    const float* bo   = (const float*)d_in[9];
    float* out = (float*)d_out;

    __half *xhi, *xlo, *qh, *kh, *vh, *ahi, *alo;
    __half *wqh, *wql, *wkh, *wkl, *wvh, *wvl, *woh, *wol;
    cudaGetSymbolAddress((void**)&xhi, g_xhi);
    cudaGetSymbolAddress((void**)&xlo, g_xlo);
    cudaGetSymbolAddress((void**)&qh,  g_qh);
    cudaGetSymbolAddress((void**)&kh,  g_kh);
    cudaGetSymbolAddress((void**)&vh,  g_vh);
    cudaGetSymbolAddress((void**)&ahi, g_ahi);
    cudaGetSymbolAddress((void**)&alo, g_alo);
    cudaGetSymbolAddress((void**)&wqh, g_wqhi);
    cudaGetSymbolAddress((void**)&wql, g_wqlo);
    cudaGetSymbolAddress((void**)&wkh, g_wkhi);
    cudaGetSymbolAddress((void**)&wkl, g_wklo);
    cudaGetSymbolAddress((void**)&wvh, g_wvhi);
    cudaGetSymbolAddress((void**)&wvl, g_wvlo);
    cudaGetSymbolAddress((void**)&woh, g_wohi);
    cudaGetSymbolAddress((void**)&wol, g_wolo);

    cudaFuncSetAttribute(gemm_mma_split<0>,
                         cudaFuncAttributeMaxDynamicSharedMemorySize, GEMM_SMEM);
    cudaFuncSetAttribute(gemm_mma_split<1>,
                         cudaFuncAttributeMaxDynamicSharedMemorySize, GEMM_SMEM);
    cudaFuncSetAttribute(attn_mma,
                         cudaFuncAttributeMaxDynamicSharedMemorySize, ATT_SMEM);

    conv_split<<<(M_*D_/4)/256, 256>>>(x, xhi, xlo, M_*D_/4);
    dim3 gw((D_*D_/4)/256, 4);
    conv_split_w<<<gw, 256>>>(Wq, Wk, Wv, Wo,
                              wqh, wql, wkh, wkl, wvh, wvl, woh, wol);

    dim3 gg(D_/128, M_/128);   // (8, 32)
    gemm_mma_split<1><<<gg, 512, GEMM_SMEM>>>(xhi, xlo, wqh, wql, bq, nullptr, qh);
    gemm_mma_split<1><<<gg, 512, GEMM_SMEM>>>(xhi, xlo, wkh, wkl, bk, nullptr, kh);
    gemm_mma_split<1><<<gg, 512, GEMM_SMEM>>>(xhi, xlo, wvh, wvl, bv, nullptr, vh);

    dim3 ga(S_/128, B_*H_);    // (16, 32)
    attn_mma<<<ga, 256, ATT_SMEM>>>(qh, kh, vh, mask, ahi, alo);

    gemm_mma_split<0><<<gg, 512, GEMM_SMEM>>>(ahi, alo, woh, wol, bo, out, nullptr);
}